// round 12
// baseline (speedup 1.0000x reference)
#include <cuda_runtime.h>
#include <cuda_bf16.h>
#include <cuda_fp16.h>
#include <cstdint>

#define BATCH   16384
#define IN_DIM  2048
#define NTREES  10
#define NDEC    255
#define CLASSES 1000
#define KDIM2   2560          // NTREES * 256
#define NPAD    1024          // padded class rows for K3 B matrix

// ---------------- device scratch ----------------
__device__ __half         g_xf[(size_t)BATCH * IN_DIM];          // x in fp16
__device__ __half         g_wf[(size_t)NTREES * 256 * IN_DIM];   // w fp16, [t][n][k]
__device__ __nv_bfloat16  g_lpb[(size_t)NPAD * KDIM2];           // [class][k] K-major
__device__ __nv_bfloat16  g_prob[(size_t)BATCH * KDIM2];

// ---------------- PTX helpers ----------------
__device__ __forceinline__ uint32_t smem_u32(const void* p) {
    uint32_t a;
    asm("{ .reg .u64 t; cvta.to.shared.u64 t, %1; cvt.u32.u64 %0, t; }" : "=r"(a) : "l"(p));
    return a;
}
#define CPA(dst, src) asm volatile("cp.async.cg.shared.global [%0], [%1], 16;" :: "r"(dst), "l"(src))
#define CPC()  asm volatile("cp.async.commit_group;" ::: "memory")
#define CPW0() asm volatile("cp.async.wait_group 0;" ::: "memory")

__device__ __forceinline__ void ldsm4(uint32_t* r, uint32_t addr) {
    asm volatile("ldmatrix.sync.aligned.m8n8.x4.shared.b16 {%0,%1,%2,%3}, [%4];"
                 : "=r"(r[0]), "=r"(r[1]), "=r"(r[2]), "=r"(r[3]) : "r"(addr));
}
__device__ __forceinline__ void mma_bf16(float* c, const uint32_t* a, const uint32_t* b) {
    asm volatile("mma.sync.aligned.m16n8k16.row.col.f32.bf16.bf16.f32 "
                 "{%0,%1,%2,%3}, {%4,%5,%6,%7}, {%8,%9}, {%0,%1,%2,%3};"
                 : "+f"(c[0]), "+f"(c[1]), "+f"(c[2]), "+f"(c[3])
                 : "r"(a[0]), "r"(a[1]), "r"(a[2]), "r"(a[3]), "r"(b[0]), "r"(b[1]));
}
// fp16 accumulate variant: C/D = 2 packed-half regs
__device__ __forceinline__ void mma_f16h(uint32_t* c, const uint32_t* a, const uint32_t* b) {
    asm volatile("mma.sync.aligned.m16n8k16.row.col.f16.f16.f16.f16 "
                 "{%0,%1}, {%2,%3,%4,%5}, {%6,%7}, {%0,%1};"
                 : "+r"(c[0]), "+r"(c[1])
                 : "r"(a[0]), "r"(a[1]), "r"(a[2]), "r"(a[3]), "r"(b[0]), "r"(b[1]));
}

// ---------------------------------------------------------------------------
// P1: x fp32 -> fp16
// ---------------------------------------------------------------------------
__global__ __launch_bounds__(256) void p1_xconv(const float* __restrict__ x) {
    size_t i = ((size_t)blockIdx.x * 256 + threadIdx.x) * 8;
    float4 v0 = *(const float4*)(x + i);
    float4 v1 = *(const float4*)(x + i + 4);
    __half2 h0 = __floats2half2_rn(v0.x, v0.y);
    __half2 h1 = __floats2half2_rn(v0.z, v0.w);
    __half2 h2 = __floats2half2_rn(v1.x, v1.y);
    __half2 h3 = __floats2half2_rn(v1.z, v1.w);
    uint4 u{*(uint32_t*)&h0, *(uint32_t*)&h1, *(uint32_t*)&h2, *(uint32_t*)&h3};
    *(uint4*)(g_xf + i) = u;
}

// ---------------------------------------------------------------------------
// P2: w_d [t][k][255] -> g_wf [t][n(256 pad)][k] fp16, K-major
// ---------------------------------------------------------------------------
__global__ __launch_bounds__(256) void p2_wconv(const float* __restrict__ wd) {
    __shared__ float sh[32][257];
    const int t = blockIdx.y, k0 = blockIdx.x * 32;
    const int n = threadIdx.x;
    const float* wp = wd + (size_t)t * IN_DIM * NDEC;
#pragma unroll
    for (int kk = 0; kk < 32; kk++)
        sh[kk][n] = (n < NDEC) ? wp[(size_t)(k0 + kk) * NDEC + n] : 0.f;
    __syncthreads();
    __half* dst = g_wf + ((size_t)t * 256 + n) * IN_DIM + k0;
#pragma unroll
    for (int u = 0; u < 4; u++) {
        __half2 p0 = __floats2half2_rn(sh[8 * u + 0][n], sh[8 * u + 1][n]);
        __half2 p1 = __floats2half2_rn(sh[8 * u + 2][n], sh[8 * u + 3][n]);
        __half2 p2 = __floats2half2_rn(sh[8 * u + 4][n], sh[8 * u + 5][n]);
        __half2 p3 = __floats2half2_rn(sh[8 * u + 6][n], sh[8 * u + 7][n]);
        uint4 v{*(uint32_t*)&p0, *(uint32_t*)&p1, *(uint32_t*)&p2, *(uint32_t*)&p3};
        *(uint4*)(dst + 8 * u) = v;
    }
}

// ---------------------------------------------------------------------------
// K1: paired softmax of w_l -> g_lpb [class][t*256+m] bf16 (K-major for K3)
// ---------------------------------------------------------------------------
__global__ __launch_bounds__(256) void k1_softmax(const float* __restrict__ wl) {
    const int blk = blockIdx.x;
    const int t = blk >> 8, m = blk & 255;
    const int tid = threadIdx.x;
    __shared__ float s[2][CLASSES];
    __shared__ float red[256];

    const float* r0 = wl + (size_t)(t * 512 + 2 * m) * CLASSES;
    for (int i = tid; i < CLASSES; i += 256) { s[0][i] = r0[i]; s[1][i] = r0[CLASSES + i]; }
    __syncthreads();

    float inv[2];
    for (int h = 0; h < 2; h++) {
        float mx = -1e30f;
        for (int i = tid; i < CLASSES; i += 256) mx = fmaxf(mx, s[h][i]);
        red[tid] = mx; __syncthreads();
        for (int o = 128; o > 0; o >>= 1) { if (tid < o) red[tid] = fmaxf(red[tid], red[tid + o]); __syncthreads(); }
        const float M = red[0]; __syncthreads();
        float sm = 0.f;
        for (int i = tid; i < CLASSES; i += 256) { float e = __expf(s[h][i] - M); s[h][i] = e; sm += e; }
        red[tid] = sm; __syncthreads();
        for (int o = 128; o > 0; o >>= 1) { if (tid < o) red[tid] += red[tid + o]; __syncthreads(); }
        inv[h] = 1.f / red[0]; __syncthreads();
    }
    const float sc = 1.f / (float)NTREES;
    for (int i = tid; i < CLASSES; i += 256)
        g_lpb[(size_t)i * KDIM2 + t * 256 + m] =
            __float2bfloat16((s[0][i] * inv[0] + s[1][i] * inv[1]) * sc);
}

// ---------------------------------------------------------------------------
// K2: fused fp16 GEMM (fp16 acc), CTA tile 128x256, 8 warps of 64x64
// grid (NTREES, BATCH/128), 256 threads, 2-stage pipeline, 2 CTAs/SM
// stage = A[128][72] + B[256][72] fp16 = 55296 B; x2 = 110592
// epilogue: P[128][264] fp16 = 67584 B (aliases stages)
// ---------------------------------------------------------------------------
#define K2_AB  18432u
#define K2_STG 55296u
__global__ __launch_bounds__(256, 2) void k2_mma() {
    extern __shared__ char smem[];
    const uint32_t sb = smem_u32(smem);
    const int t    = blockIdx.x;
    const int row0 = blockIdx.y * 128;
    const int tid  = threadIdx.x;
    const int lane = tid & 31, wid = tid >> 5;
    const int wm = wid & 1, wn = wid >> 1;     // 2 x 4 warps: 64 rows x 64 cols

    const __half* pA = g_xf + (size_t)row0 * IN_DIM;
    const __half* pB = g_wf + (size_t)t * 256 * IN_DIM;

    // ldmatrix per-lane byte offsets (stride 72 halves = 144 B)
    const int arow = lane & 15, akof = (lane >> 4) * 8;
    uint32_t aoff[4];
#pragma unroll
    for (int mt = 0; mt < 4; mt++)
        aoff[mt] = ((wm * 64 + mt * 16 + arow) * 72 + akof) * 2;
    const int bg = lane >> 3;
    const int brow = ((bg >> 1) * 8) + (lane & 7);
    const int bkof = (bg & 1) * 8;
    uint32_t boff[4];
#pragma unroll
    for (int q = 0; q < 4; q++)
        boff[q] = ((wn * 64 + q * 16 + brow) * 72 + bkof) * 2;

    uint32_t acc[4][8][2];    // packed fp16 accumulators
#pragma unroll
    for (int a = 0; a < 4; a++)
#pragma unroll
        for (int b = 0; b < 8; b++) { acc[a][b][0] = 0u; acc[a][b][1] = 0u; }

    const int NC = IN_DIM / 64;   // 32 chunks of k=64

#define K2_LOAD(cc, stg) do {                                                     \
        const uint32_t st_ = sb + (uint32_t)(stg) * K2_STG;                       \
        const int k0_ = (cc) * 64;                                                \
        _Pragma("unroll")                                                         \
        for (int i_ = 0; i_ < 4; i_++) {                                          \
            int idx_ = tid + i_ * 256;                                            \
            int row_ = idx_ >> 3, ch_ = idx_ & 7;                                 \
            uint32_t d_ = st_ + row_ * 144 + ch_ * 16;                            \
            CPA(d_, (const char*)(pA + (size_t)row_ * IN_DIM + k0_ + ch_ * 8));   \
        }                                                                         \
        _Pragma("unroll")                                                         \
        for (int i_ = 0; i_ < 8; i_++) {                                          \
            int idx_ = tid + i_ * 256;                                            \
            int row_ = idx_ >> 3, ch_ = idx_ & 7;                                 \
            uint32_t d_ = st_ + K2_AB + row_ * 144 + ch_ * 16;                    \
            CPA(d_, (const char*)(pB + (size_t)row_ * IN_DIM + k0_ + ch_ * 8));   \
        }                                                                         \
    } while (0)

    K2_LOAD(0, 0); CPC();

    for (int c = 0; c < NC; c++) {
        CPW0();
        __syncthreads();
        if (c + 1 < NC) K2_LOAD(c + 1, (c + 1) & 1);
        CPC();
        const uint32_t st = sb + (uint32_t)(c & 1) * K2_STG;
#pragma unroll
        for (int ks = 0; ks < 4; ks++) {
            const uint32_t kb = ks * 32;      // 16 halves
            uint32_t a[4][4];
#pragma unroll
            for (int mt = 0; mt < 4; mt++)
                ldsm4(a[mt], st + aoff[mt] + kb);
#pragma unroll
            for (int q = 0; q < 4; q++) {
                uint32_t b[4];
                ldsm4(b, st + K2_AB + boff[q] + kb);
#pragma unroll
                for (int mt = 0; mt < 4; mt++) {
                    mma_f16h(acc[mt][2 * q],     a[mt], b + 0);
                    mma_f16h(acc[mt][2 * q + 1], a[mt], b + 2);
                }
            }
        }
    }
    __syncthreads();

    // ---------- fused epilogue: sigmoid -> P[128][264] fp16, tree products ---
    __half* P = (__half*)smem;
    const int cbase = wn * 64 + 2 * (lane & 3);
    const int rbase = wm * 64 + (lane >> 2);
#pragma unroll
    for (int mt = 0; mt < 4; mt++)
#pragma unroll
        for (int j = 0; j < 8; j++) {
            const int col = cbase + j * 8;
            const int row = rbase + mt * 16;
            float2 lo = __half22float2(*(__half2*)&acc[mt][j][0]);   // row
            float2 hi = __half22float2(*(__half2*)&acc[mt][j][1]);   // row+8
            __half2 slo = __floats2half2_rn(1.f / (1.f + __expf(-lo.x)),
                                            1.f / (1.f + __expf(-lo.y)));
            __half2 shi = __floats2half2_rn(1.f / (1.f + __expf(-hi.x)),
                                            1.f / (1.f + __expf(-hi.y)));
            *(__half2*)(P + row * 264 + col)       = slo;
            *(__half2*)(P + (row + 8) * 264 + col) = shi;
        }
    __syncthreads();

    const int m = tid;             // 0..255 leaves
    __nv_bfloat16* dst = g_prob + (size_t)row0 * KDIM2 + t * 256 + m;
    for (int r = 0; r < 128; r++) {
        const __half* Pr = P + r * 264;
        float prod = 1.f;
#pragma unroll
        for (int n = 0; n < 8; n++) {
            int node = (1 << n) - 1 + (m >> (8 - n));
            float p = __half2float(Pr[node]);
            prod *= ((m >> (7 - n)) & 1) ? (1.f - p) : p;
        }
        dst[(size_t)r * KDIM2] = __float2bfloat16(prod);
    }
#undef K2_LOAD
}

// ---------------------------------------------------------------------------
// K3: bf16 mma GEMM out[64x256] = prob[64x2560] * leafp^T, 8 warps 32x64
// grid (4, BATCH/64), 256 threads, 2-stage pipeline (1 sync/chunk), 2 CTAs/SM
// stage = A[64][72] + B[256][72] bf16 = 46080 B; x2 = 92160
// ---------------------------------------------------------------------------
#define K3_AB  9216u
#define K3_STG 46080u
__global__ __launch_bounds__(256, 2) void k3_mma(float* __restrict__ out) {
    extern __shared__ char smem[];
    const uint32_t sb = smem_u32(smem);
    const int ct   = blockIdx.x;
    const int row0 = blockIdx.y * 64;
    const int tid  = threadIdx.x;
    const int lane = tid & 31, wid = tid >> 5;
    const int wm = wid & 1, wn = wid >> 1;

    const __nv_bfloat16* pA = g_prob + (size_t)row0 * KDIM2;
    const __nv_bfloat16* pB = g_lpb + (size_t)(ct * 256) * KDIM2;

    const int arow = lane & 15, akof = (lane >> 4) * 8;
    const uint32_t aoff0 = ((wm * 32 + arow) * 72 + akof) * 2;
    const uint32_t aoff1 = ((wm * 32 + 16 + arow) * 72 + akof) * 2;
    const int bg = lane >> 3;
    const int brow = ((bg >> 1) * 8) + (lane & 7);
    const int bkof = (bg & 1) * 8;
    uint32_t boff[4];
#pragma unroll
    for (int q = 0; q < 4; q++)
        boff[q] = ((wn * 64 + q * 16 + brow) * 72 + bkof) * 2;

    float acc[2][8][4];
#pragma unroll
    for (int a = 0; a < 2; a++)
#pragma unroll
        for (int b = 0; b < 8; b++)
#pragma unroll
            for (int c = 0; c < 4; c++) acc[a][b][c] = 0.f;

    const int NC = KDIM2 / 64;   // 40

#define K3_LOAD(cc, stg) do {                                                     \
        const uint32_t st_ = sb + (uint32_t)(stg) * K3_STG;                       \
        const int k0_ = (cc) * 64;                                                \
        _Pragma("unroll")                                                         \
        for (int i_ = 0; i_ < 2; i_++) {                                          \
            int idx_ = tid + i_ * 256;                                            \
            int row_ = idx_ >> 3, ch_ = idx_ & 7;                                 \
            uint32_t d_ = st_ + row_ * 144 + ch_ * 16;                            \
            CPA(d_, (const char*)(pA + (size_t)row_ * KDIM2 + k0_ + ch_ * 8));    \
        }                                                                         \
        _Pragma("unroll")                                                         \
        for (int i_ = 0; i_ < 8; i_++) {                                          \
            int idx_ = tid + i_ * 256;                                            \
            int row_ = idx_ >> 3, ch_ = idx_ & 7;                                 \
            uint32_t d_ = st_ + K3_AB + row_ * 144 + ch_ * 16;                    \
            CPA(d_, (const char*)(pB + (size_t)row_ * KDIM2 + k0_ + ch_ * 8));    \
        }                                                                         \
    } while (0)

    K3_LOAD(0, 0); CPC();

    for (int c = 0; c < NC; c++) {
        CPW0();
        __syncthreads();
        if (c + 1 < NC) K3_LOAD(c + 1, (c + 1) & 1);
        CPC();
        const uint32_t st = sb + (uint32_t)(c & 1) * K3_STG;
#pragma unroll
        for (int ks = 0; ks < 4; ks++) {
            const uint32_t kb = ks * 32;
            uint32_t a[2][4];
            ldsm4(a[0], st + aoff0 + kb);
            ldsm4(a[1], st + aoff1 + kb);
#pragma unroll
            for (int q = 0; q < 4; q++) {
                uint32_t b[4];
                ldsm4(b, st + K3_AB + boff[q] + kb);
                mma_bf16(acc[0][2 * q],     a[0], b + 0);
                mma_bf16(acc[0][2 * q + 1], a[0], b + 2);
                mma_bf16(acc[1][2 * q],     a[1], b + 0);
                mma_bf16(acc[1][2 * q + 1], a[1], b + 2);
            }
        }
    }

    const int cbase = ct * 256 + wn * 64 + 2 * (lane & 3);
    const int rbase = row0 + wm * 32 + (lane >> 2);
#pragma unroll
    for (int mt = 0; mt < 2; mt++)
#pragma unroll
        for (int j = 0; j < 8; j++) {
            int col = cbase + j * 8;
            int r0w = rbase + mt * 16;
            if (col + 1 < CLASSES) {
                *(float2*)(out + (size_t)r0w * CLASSES + col) = make_float2(acc[mt][j][0], acc[mt][j][1]);
                *(float2*)(out + (size_t)(r0w + 8) * CLASSES + col) = make_float2(acc[mt][j][2], acc[mt][j][3]);
            } else if (col < CLASSES) {
                out[(size_t)r0w * CLASSES + col] = acc[mt][j][0];
                out[(size_t)(r0w + 8) * CLASSES + col] = acc[mt][j][2];
            }
        }
#undef K3_LOAD
}

// ---------------------------------------------------------------------------
extern "C" void kernel_launch(void* const* d_in, const int* in_sizes, int n_in,
                              void* d_out, int out_size) {
    const float* x = nullptr;
    const float* wd = nullptr;
    const float* wl = nullptr;
    for (int i = 0; i < n_in; i++) {
        if (in_sizes[i] == BATCH * IN_DIM)              x = (const float*)d_in[i];
        else if (in_sizes[i] == NTREES * IN_DIM * NDEC) wd = (const float*)d_in[i];
        else if (in_sizes[i] == NTREES * 512 * CLASSES) wl = (const float*)d_in[i];
    }
    float* out = (float*)d_out;

    cudaFuncSetAttribute(k2_mma, cudaFuncAttributeMaxDynamicSharedMemorySize, 2 * K2_STG);
    cudaFuncSetAttribute(k3_mma, cudaFuncAttributeMaxDynamicSharedMemorySize, 2 * K3_STG);

    p1_xconv<<<BATCH * IN_DIM / 8 / 256, 256>>>(x);
    p2_wconv<<<dim3(IN_DIM / 32, NTREES), 256>>>(wd);
    k1_softmax<<<NTREES * 256, 256>>>(wl);
    k2_mma<<<dim3(NTREES, BATCH / 128), 256, 2 * K2_STG>>>();
    k3_mma<<<dim3(4, BATCH / 64), 256, 2 * K3_STG>>>(out);
}

// round 13
// speedup vs baseline: 1.0046x; 1.0046x over previous
#include <cuda_runtime.h>
#include <cuda_bf16.h>
#include <cuda_fp16.h>
#include <cstdint>

#define BATCH   16384
#define BATCH_P 16416         // padded rows for K3's 96-row tiles
#define IN_DIM  2048
#define NTREES  10
#define NDEC    255
#define CLASSES 1000
#define KDIM2   2560          // NTREES * 256
#define NPAD    1024          // padded class rows for K3 B matrix

// ---------------- device scratch ----------------
__device__ __half         g_xf[(size_t)BATCH * IN_DIM];          // x in fp16
__device__ __half         g_wf[(size_t)NTREES * 256 * IN_DIM];   // w fp16, [t][n][k]
__device__ __nv_bfloat16  g_lpb[(size_t)NPAD * KDIM2];           // [class][k] K-major
__device__ __nv_bfloat16  g_prob[(size_t)BATCH_P * KDIM2];       // padded (rows>=16384 stay 0)

// ---------------- PTX helpers ----------------
__device__ __forceinline__ uint32_t smem_u32(const void* p) {
    uint32_t a;
    asm("{ .reg .u64 t; cvta.to.shared.u64 t, %1; cvt.u32.u64 %0, t; }" : "=r"(a) : "l"(p));
    return a;
}
#define CPA(dst, src) asm volatile("cp.async.cg.shared.global [%0], [%1], 16;" :: "r"(dst), "l"(src))
#define CPC()  asm volatile("cp.async.commit_group;" ::: "memory")
#define CPW0() asm volatile("cp.async.wait_group 0;" ::: "memory")

__device__ __forceinline__ void ldsm4(uint32_t* r, uint32_t addr) {
    asm volatile("ldmatrix.sync.aligned.m8n8.x4.shared.b16 {%0,%1,%2,%3}, [%4];"
                 : "=r"(r[0]), "=r"(r[1]), "=r"(r[2]), "=r"(r[3]) : "r"(addr));
}
__device__ __forceinline__ void mma_bf16(float* c, const uint32_t* a, const uint32_t* b) {
    asm volatile("mma.sync.aligned.m16n8k16.row.col.f32.bf16.bf16.f32 "
                 "{%0,%1,%2,%3}, {%4,%5,%6,%7}, {%8,%9}, {%0,%1,%2,%3};"
                 : "+f"(c[0]), "+f"(c[1]), "+f"(c[2]), "+f"(c[3])
                 : "r"(a[0]), "r"(a[1]), "r"(a[2]), "r"(a[3]), "r"(b[0]), "r"(b[1]));
}
// fp16 accumulate variant: C/D = 2 packed-half regs
__device__ __forceinline__ void mma_f16h(uint32_t* c, const uint32_t* a, const uint32_t* b) {
    asm volatile("mma.sync.aligned.m16n8k16.row.col.f16.f16.f16.f16 "
                 "{%0,%1}, {%2,%3,%4,%5}, {%6,%7}, {%0,%1};"
                 : "+r"(c[0]), "+r"(c[1])
                 : "r"(a[0]), "r"(a[1]), "r"(a[2]), "r"(a[3]), "r"(b[0]), "r"(b[1]));
}

// ---------------------------------------------------------------------------
// K0: fused prelude — P1 (x->fp16), P2 (w_d -> K-major fp16), K1 (softmax)
// grid = 16384 + 640 + 2560 = 19584 blocks, 256 threads
// ---------------------------------------------------------------------------
#define P1_BLKS 16384
#define P2_BLKS 640
__global__ __launch_bounds__(256) void k0_prep(const float* __restrict__ x,
                                               const float* __restrict__ wd,
                                               const float* __restrict__ wl) {
    const int bid = blockIdx.x;
    const int tid = threadIdx.x;

    if (bid < P1_BLKS) {
        // ---- P1: x fp32 -> fp16, 8 elems/thread ----
        size_t i = ((size_t)bid * 256 + tid) * 8;
        float4 v0 = *(const float4*)(x + i);
        float4 v1 = *(const float4*)(x + i + 4);
        __half2 h0 = __floats2half2_rn(v0.x, v0.y);
        __half2 h1 = __floats2half2_rn(v0.z, v0.w);
        __half2 h2 = __floats2half2_rn(v1.x, v1.y);
        __half2 h3 = __floats2half2_rn(v1.z, v1.w);
        uint4 u{*(uint32_t*)&h0, *(uint32_t*)&h1, *(uint32_t*)&h2, *(uint32_t*)&h3};
        *(uint4*)(g_xf + i) = u;
        return;
    }

    if (bid < P1_BLKS + P2_BLKS) {
        // ---- P2: w_d [t][k][255] -> g_wf [t][n][k] fp16 K-major ----
        __shared__ float sh[32][257];
        const int blk = bid - P1_BLKS;       // 0..639
        const int t = blk >> 6;              // 0..9
        const int k0 = (blk & 63) * 32;
        const int n = tid;
        const float* wp = wd + (size_t)t * IN_DIM * NDEC;
#pragma unroll
        for (int kk = 0; kk < 32; kk++)
            sh[kk][n] = (n < NDEC) ? wp[(size_t)(k0 + kk) * NDEC + n] : 0.f;
        __syncthreads();
        __half* dst = g_wf + ((size_t)t * 256 + n) * IN_DIM + k0;
#pragma unroll
        for (int u = 0; u < 4; u++) {
            __half2 p0 = __floats2half2_rn(sh[8 * u + 0][n], sh[8 * u + 1][n]);
            __half2 p1 = __floats2half2_rn(sh[8 * u + 2][n], sh[8 * u + 3][n]);
            __half2 p2 = __floats2half2_rn(sh[8 * u + 4][n], sh[8 * u + 5][n]);
            __half2 p3 = __floats2half2_rn(sh[8 * u + 6][n], sh[8 * u + 7][n]);
            uint4 v{*(uint32_t*)&p0, *(uint32_t*)&p1, *(uint32_t*)&p2, *(uint32_t*)&p3};
            *(uint4*)(dst + 8 * u) = v;
        }
        return;
    }

    // ---- K1: paired softmax of w_l -> g_lpb [class][t*256+m] bf16 ----
    {
        __shared__ float s[2][CLASSES];
        __shared__ float red[256];
        const int blk = bid - P1_BLKS - P2_BLKS;   // 0..2559
        const int t = blk >> 8, m = blk & 255;

        const float* r0 = wl + (size_t)(t * 512 + 2 * m) * CLASSES;
        for (int i = tid; i < CLASSES; i += 256) { s[0][i] = r0[i]; s[1][i] = r0[CLASSES + i]; }
        __syncthreads();

        float inv[2];
        for (int h = 0; h < 2; h++) {
            float mx = -1e30f;
            for (int i = tid; i < CLASSES; i += 256) mx = fmaxf(mx, s[h][i]);
            red[tid] = mx; __syncthreads();
            for (int o = 128; o > 0; o >>= 1) { if (tid < o) red[tid] = fmaxf(red[tid], red[tid + o]); __syncthreads(); }
            const float M = red[0]; __syncthreads();
            float sm = 0.f;
            for (int i = tid; i < CLASSES; i += 256) { float e = __expf(s[h][i] - M); s[h][i] = e; sm += e; }
            red[tid] = sm; __syncthreads();
            for (int o = 128; o > 0; o >>= 1) { if (tid < o) red[tid] += red[tid + o]; __syncthreads(); }
            inv[h] = 1.f / red[0]; __syncthreads();
        }
        const float sc = 1.f / (float)NTREES;
        for (int i = tid; i < CLASSES; i += 256)
            g_lpb[(size_t)i * KDIM2 + t * 256 + m] =
                __float2bfloat16((s[0][i] * inv[0] + s[1][i] * inv[1]) * sc);
    }
}

// ---------------------------------------------------------------------------
// K2: fused fp16 GEMM (fp16 acc), CTA tile 128x256, 8 warps of 64x64
// grid (NTREES, BATCH/128), 256 threads, 2-stage pipeline, 2 CTAs/SM
// stage = A[128][72] + B[256][72] fp16 = 55296 B; x2 = 110592
// ---------------------------------------------------------------------------
#define K2_AB  18432u
#define K2_STG 55296u
__global__ __launch_bounds__(256, 2) void k2_mma() {
    extern __shared__ char smem[];
    const uint32_t sb = smem_u32(smem);
    const int t    = blockIdx.x;
    const int row0 = blockIdx.y * 128;
    const int tid  = threadIdx.x;
    const int lane = tid & 31, wid = tid >> 5;
    const int wm = wid & 1, wn = wid >> 1;     // 2 x 4 warps: 64 rows x 64 cols

    const __half* pA = g_xf + (size_t)row0 * IN_DIM;
    const __half* pB = g_wf + (size_t)t * 256 * IN_DIM;

    const int arow = lane & 15, akof = (lane >> 4) * 8;
    uint32_t aoff[4];
#pragma unroll
    for (int mt = 0; mt < 4; mt++)
        aoff[mt] = ((wm * 64 + mt * 16 + arow) * 72 + akof) * 2;
    const int bg = lane >> 3;
    const int brow = ((bg >> 1) * 8) + (lane & 7);
    const int bkof = (bg & 1) * 8;
    uint32_t boff[4];
#pragma unroll
    for (int q = 0; q < 4; q++)
        boff[q] = ((wn * 64 + q * 16 + brow) * 72 + bkof) * 2;

    uint32_t acc[4][8][2];    // packed fp16 accumulators
#pragma unroll
    for (int a = 0; a < 4; a++)
#pragma unroll
        for (int b = 0; b < 8; b++) { acc[a][b][0] = 0u; acc[a][b][1] = 0u; }

    const int NC = IN_DIM / 64;   // 32 chunks of k=64

#define K2_LOAD(cc, stg) do {                                                     \
        const uint32_t st_ = sb + (uint32_t)(stg) * K2_STG;                       \
        const int k0_ = (cc) * 64;                                                \
        _Pragma("unroll")                                                         \
        for (int i_ = 0; i_ < 4; i_++) {                                          \
            int idx_ = tid + i_ * 256;                                            \
            int row_ = idx_ >> 3, ch_ = idx_ & 7;                                 \
            uint32_t d_ = st_ + row_ * 144 + ch_ * 16;                            \
            CPA(d_, (const char*)(pA + (size_t)row_ * IN_DIM + k0_ + ch_ * 8));   \
        }                                                                         \
        _Pragma("unroll")                                                         \
        for (int i_ = 0; i_ < 8; i_++) {                                          \
            int idx_ = tid + i_ * 256;                                            \
            int row_ = idx_ >> 3, ch_ = idx_ & 7;                                 \
            uint32_t d_ = st_ + K2_AB + row_ * 144 + ch_ * 16;                    \
            CPA(d_, (const char*)(pB + (size_t)row_ * IN_DIM + k0_ + ch_ * 8));   \
        }                                                                         \
    } while (0)

    K2_LOAD(0, 0); CPC();

    for (int c = 0; c < NC; c++) {
        CPW0();
        __syncthreads();
        if (c + 1 < NC) K2_LOAD(c + 1, (c + 1) & 1);
        CPC();
        const uint32_t st = sb + (uint32_t)(c & 1) * K2_STG;
#pragma unroll
        for (int ks = 0; ks < 4; ks++) {
            const uint32_t kb = ks * 32;      // 16 halves
            uint32_t a[4][4];
#pragma unroll
            for (int mt = 0; mt < 4; mt++)
                ldsm4(a[mt], st + aoff[mt] + kb);
#pragma unroll
            for (int q = 0; q < 4; q++) {
                uint32_t b[4];
                ldsm4(b, st + K2_AB + boff[q] + kb);
#pragma unroll
                for (int mt = 0; mt < 4; mt++) {
                    mma_f16h(acc[mt][2 * q],     a[mt], b + 0);
                    mma_f16h(acc[mt][2 * q + 1], a[mt], b + 2);
                }
            }
        }
    }
    __syncthreads();

    // ---------- fused epilogue: sigmoid -> P[128][264] fp16, tree products ---
    __half* P = (__half*)smem;
    const int cbase = wn * 64 + 2 * (lane & 3);
    const int rbase = wm * 64 + (lane >> 2);
#pragma unroll
    for (int mt = 0; mt < 4; mt++)
#pragma unroll
        for (int j = 0; j < 8; j++) {
            const int col = cbase + j * 8;
            const int row = rbase + mt * 16;
            float2 lo = __half22float2(*(__half2*)&acc[mt][j][0]);   // row
            float2 hi = __half22float2(*(__half2*)&acc[mt][j][1]);   // row+8
            __half2 slo = __floats2half2_rn(1.f / (1.f + __expf(-lo.x)),
                                            1.f / (1.f + __expf(-lo.y)));
            __half2 shi = __floats2half2_rn(1.f / (1.f + __expf(-hi.x)),
                                            1.f / (1.f + __expf(-hi.y)));
            *(__half2*)(P + row * 264 + col)       = slo;
            *(__half2*)(P + (row + 8) * 264 + col) = shi;
        }
    __syncthreads();

    const int m = tid;             // 0..255 leaves
    __nv_bfloat16* dst = g_prob + (size_t)row0 * KDIM2 + t * 256 + m;
    for (int r = 0; r < 128; r++) {
        const __half* Pr = P + r * 264;
        float prod = 1.f;
#pragma unroll
        for (int n = 0; n < 8; n++) {
            int node = (1 << n) - 1 + (m >> (8 - n));
            float p = __half2float(Pr[node]);
            prod *= ((m >> (7 - n)) & 1) ? (1.f - p) : p;
        }
        dst[(size_t)r * KDIM2] = __float2bfloat16(prod);
    }
#undef K2_LOAD
}

// ---------------------------------------------------------------------------
// K3: bf16 mma GEMM out[96x256] = prob[96x2560] * leafp^T, 8 warps of 48x64
// grid (4, 171), 256 threads, 2-stage pipeline (1 sync/chunk), 2 CTAs/SM
// stage = A[96][72] + B[256][72] bf16 = 50688 B; x2 = 101376
// ---------------------------------------------------------------------------
#define K3_AB  13824u
#define K3_STG 50688u
__global__ __launch_bounds__(256, 2) void k3_mma(float* __restrict__ out) {
    extern __shared__ char smem[];
    const uint32_t sb = smem_u32(smem);
    const int ct   = blockIdx.x;
    const int row0 = blockIdx.y * 96;
    const int tid  = threadIdx.x;
    const int lane = tid & 31, wid = tid >> 5;
    const int wm = wid & 1, wn = wid >> 1;    // 2 x 4 warps: 48 rows x 64 cols

    const __nv_bfloat16* pA = g_prob + (size_t)row0 * KDIM2;
    const __nv_bfloat16* pB = g_lpb + (size_t)(ct * 256) * KDIM2;

    const int arow = lane & 15, akof = (lane >> 4) * 8;
    uint32_t aoff[3];
#pragma unroll
    for (int mt = 0; mt < 3; mt++)
        aoff[mt] = ((wm * 48 + mt * 16 + arow) * 72 + akof) * 2;
    const int bg = lane >> 3;
    const int brow = ((bg >> 1) * 8) + (lane & 7);
    const int bkof = (bg & 1) * 8;
    uint32_t boff[4];
#pragma unroll
    for (int q = 0; q < 4; q++)
        boff[q] = ((wn * 64 + q * 16 + brow) * 72 + bkof) * 2;

    float acc[3][8][4];
#pragma unroll
    for (int a = 0; a < 3; a++)
#pragma unroll
        for (int b = 0; b < 8; b++)
#pragma unroll
            for (int c = 0; c < 4; c++) acc[a][b][c] = 0.f;

    const int NC = KDIM2 / 64;   // 40

#define K3_LOAD(cc, stg) do {                                                     \
        const uint32_t st_ = sb + (uint32_t)(stg) * K3_STG;                       \
        const int k0_ = (cc) * 64;                                                \
        _Pragma("unroll")                                                         \
        for (int i_ = 0; i_ < 3; i_++) {                                          \
            int idx_ = tid + i_ * 256;                                            \
            int row_ = idx_ >> 3, ch_ = idx_ & 7;                                 \
            uint32_t d_ = st_ + row_ * 144 + ch_ * 16;                            \
            CPA(d_, (const char*)(pA + (size_t)row_ * KDIM2 + k0_ + ch_ * 8));    \
        }                                                                         \
        _Pragma("unroll")                                                         \
        for (int i_ = 0; i_ < 8; i_++) {                                          \
            int idx_ = tid + i_ * 256;                                            \
            int row_ = idx_ >> 3, ch_ = idx_ & 7;                                 \
            uint32_t d_ = st_ + K3_AB + row_ * 144 + ch_ * 16;                    \
            CPA(d_, (const char*)(pB + (size_t)row_ * KDIM2 + k0_ + ch_ * 8));    \
        }                                                                         \
    } while (0)

    K3_LOAD(0, 0); CPC();

    for (int c = 0; c < NC; c++) {
        CPW0();
        __syncthreads();
        if (c + 1 < NC) K3_LOAD(c + 1, (c + 1) & 1);
        CPC();
        const uint32_t st = sb + (uint32_t)(c & 1) * K3_STG;
#pragma unroll
        for (int ks = 0; ks < 4; ks++) {
            const uint32_t kb = ks * 32;
            uint32_t a[3][4];
#pragma unroll
            for (int mt = 0; mt < 3; mt++)
                ldsm4(a[mt], st + aoff[mt] + kb);
#pragma unroll
            for (int q = 0; q < 4; q++) {
                uint32_t b[4];
                ldsm4(b, st + K3_AB + boff[q] + kb);
#pragma unroll
                for (int mt = 0; mt < 3; mt++) {
                    mma_bf16(acc[mt][2 * q],     a[mt], b + 0);
                    mma_bf16(acc[mt][2 * q + 1], a[mt], b + 2);
                }
            }
        }
    }

    const int cbase = ct * 256 + wn * 64 + 2 * (lane & 3);
    const int rbase = row0 + wm * 48 + (lane >> 2);
#pragma unroll
    for (int mt = 0; mt < 3; mt++)
#pragma unroll
        for (int j = 0; j < 8; j++) {
            int col = cbase + j * 8;
            int r0w = rbase + mt * 16;
            if (col + 1 < CLASSES) {
                if (r0w < BATCH)
                    *(float2*)(out + (size_t)r0w * CLASSES + col) = make_float2(acc[mt][j][0], acc[mt][j][1]);
                if (r0w + 8 < BATCH)
                    *(float2*)(out + (size_t)(r0w + 8) * CLASSES + col) = make_float2(acc[mt][j][2], acc[mt][j][3]);
            } else if (col < CLASSES) {
                if (r0w < BATCH)     out[(size_t)r0w * CLASSES + col] = acc[mt][j][0];
                if (r0w + 8 < BATCH) out[(size_t)(r0w + 8) * CLASSES + col] = acc[mt][j][2];
            }
        }
#undef K3_LOAD
}

// ---------------------------------------------------------------------------
extern "C" void kernel_launch(void* const* d_in, const int* in_sizes, int n_in,
                              void* d_out, int out_size) {
    const float* x = nullptr;
    const float* wd = nullptr;
    const float* wl = nullptr;
    for (int i = 0; i < n_in; i++) {
        if (in_sizes[i] == BATCH * IN_DIM)              x = (const float*)d_in[i];
        else if (in_sizes[i] == NTREES * IN_DIM * NDEC) wd = (const float*)d_in[i];
        else if (in_sizes[i] == NTREES * 512 * CLASSES) wl = (const float*)d_in[i];
    }
    float* out = (float*)d_out;

    cudaFuncSetAttribute(k2_mma, cudaFuncAttributeMaxDynamicSharedMemorySize, 2 * K2_STG);
    cudaFuncSetAttribute(k3_mma, cudaFuncAttributeMaxDynamicSharedMemorySize, 2 * K3_STG);

    k0_prep<<<P1_BLKS + P2_BLKS + NTREES * 256, 256>>>(x, wd, wl);
    k2_mma<<<dim3(NTREES, BATCH / 128), 256, 2 * K2_STG>>>();
    k3_mma<<<dim3(4, (BATCH + 95) / 96), 256, 2 * K3_STG>>>(out);
}

// round 14
// speedup vs baseline: 1.0053x; 1.0007x over previous
#include <cuda_runtime.h>
#include <cuda_bf16.h>
#include <cuda_fp16.h>
#include <cstdint>

#define BATCH   16384
#define BATCH_P 16416         // padded rows for K3's 96-row tiles
#define IN_DIM  2048
#define NTREES  10
#define NDEC    255
#define CLASSES 1000
#define KDIM2   2560          // NTREES * 256
#define NPAD    1024          // padded class rows for K3 B matrix

// ---------------- device scratch ----------------
__device__ __half         g_xf[(size_t)BATCH * IN_DIM];          // x in fp16
__device__ __half         g_wf[(size_t)NTREES * 256 * IN_DIM];   // w fp16, [t][n][k]
__device__ __nv_bfloat16  g_lpb[(size_t)NPAD * KDIM2];           // [class][k] K-major
__device__ __nv_bfloat16  g_prob[(size_t)BATCH_P * KDIM2];       // padded (rows>=16384 stay 0)

// ---------------- PTX helpers ----------------
__device__ __forceinline__ uint32_t smem_u32(const void* p) {
    uint32_t a;
    asm("{ .reg .u64 t; cvta.to.shared.u64 t, %1; cvt.u32.u64 %0, t; }" : "=r"(a) : "l"(p));
    return a;
}
#define CPA(dst, src) asm volatile("cp.async.cg.shared.global [%0], [%1], 16;" :: "r"(dst), "l"(src))
#define CPC()  asm volatile("cp.async.commit_group;" ::: "memory")
#define CPW0() asm volatile("cp.async.wait_group 0;" ::: "memory")

__device__ __forceinline__ void ldsm4(uint32_t* r, uint32_t addr) {
    asm volatile("ldmatrix.sync.aligned.m8n8.x4.shared.b16 {%0,%1,%2,%3}, [%4];"
                 : "=r"(r[0]), "=r"(r[1]), "=r"(r[2]), "=r"(r[3]) : "r"(addr));
}
__device__ __forceinline__ void mma_bf16(float* c, const uint32_t* a, const uint32_t* b) {
    asm volatile("mma.sync.aligned.m16n8k16.row.col.f32.bf16.bf16.f32 "
                 "{%0,%1,%2,%3}, {%4,%5,%6,%7}, {%8,%9}, {%0,%1,%2,%3};"
                 : "+f"(c[0]), "+f"(c[1]), "+f"(c[2]), "+f"(c[3])
                 : "r"(a[0]), "r"(a[1]), "r"(a[2]), "r"(a[3]), "r"(b[0]), "r"(b[1]));
}
// fp16 accumulate variant: C/D = 2 packed-half regs
__device__ __forceinline__ void mma_f16h(uint32_t* c, const uint32_t* a, const uint32_t* b) {
    asm volatile("mma.sync.aligned.m16n8k16.row.col.f16.f16.f16.f16 "
                 "{%0,%1}, {%2,%3,%4,%5}, {%6,%7}, {%0,%1};"
                 : "+r"(c[0]), "+r"(c[1])
                 : "r"(a[0]), "r"(a[1]), "r"(a[2]), "r"(a[3]), "r"(b[0]), "r"(b[1]));
}

// ---------------------------------------------------------------------------
// K0: fused prelude — K1 (softmax) FIRST, then P2, then P1 (BW-bound fill)
// grid = 2560 + 640 + 8192 = 11392 blocks, 256 threads
// ---------------------------------------------------------------------------
#define K1_BLKS 2560
#define P2_BLKS 640
#define P1_BLKS 8192          // 16 floats per thread
__global__ __launch_bounds__(256) void k0_prep(const float* __restrict__ x,
                                               const float* __restrict__ wd,
                                               const float* __restrict__ wl) {
    const int bid = blockIdx.x;
    const int tid = threadIdx.x;

    if (bid < K1_BLKS) {
        // ---- K1: paired softmax of w_l -> g_lpb [class][t*256+m] bf16 ----
        __shared__ float s[2][CLASSES];
        __shared__ float red[256];
        const int t = bid >> 8, m = bid & 255;

        const float* r0 = wl + (size_t)(t * 512 + 2 * m) * CLASSES;
        for (int i = tid; i < CLASSES; i += 256) { s[0][i] = r0[i]; s[1][i] = r0[CLASSES + i]; }
        __syncthreads();

        float inv[2];
        for (int h = 0; h < 2; h++) {
            float mx = -1e30f;
            for (int i = tid; i < CLASSES; i += 256) mx = fmaxf(mx, s[h][i]);
            red[tid] = mx; __syncthreads();
            for (int o = 128; o > 0; o >>= 1) { if (tid < o) red[tid] = fmaxf(red[tid], red[tid + o]); __syncthreads(); }
            const float M = red[0]; __syncthreads();
            float sm = 0.f;
            for (int i = tid; i < CLASSES; i += 256) { float e = __expf(s[h][i] - M); s[h][i] = e; sm += e; }
            red[tid] = sm; __syncthreads();
            for (int o = 128; o > 0; o >>= 1) { if (tid < o) red[tid] += red[tid + o]; __syncthreads(); }
            inv[h] = 1.f / red[0]; __syncthreads();
        }
        const float sc = 1.f / (float)NTREES;
        for (int i = tid; i < CLASSES; i += 256)
            g_lpb[(size_t)i * KDIM2 + t * 256 + m] =
                __float2bfloat16((s[0][i] * inv[0] + s[1][i] * inv[1]) * sc);
        return;
    }

    if (bid < K1_BLKS + P2_BLKS) {
        // ---- P2: w_d [t][k][255] -> g_wf [t][n][k] fp16 K-major ----
        __shared__ float sh[32][257];
        const int blk = bid - K1_BLKS;       // 0..639
        const int t = blk >> 6;              // 0..9
        const int k0 = (blk & 63) * 32;
        const int n = tid;
        const float* wp = wd + (size_t)t * IN_DIM * NDEC;
#pragma unroll
        for (int kk = 0; kk < 32; kk++)
            sh[kk][n] = (n < NDEC) ? wp[(size_t)(k0 + kk) * NDEC + n] : 0.f;
        __syncthreads();
        __half* dst = g_wf + ((size_t)t * 256 + n) * IN_DIM + k0;
#pragma unroll
        for (int u = 0; u < 4; u++) {
            __half2 p0 = __floats2half2_rn(sh[8 * u + 0][n], sh[8 * u + 1][n]);
            __half2 p1 = __floats2half2_rn(sh[8 * u + 2][n], sh[8 * u + 3][n]);
            __half2 p2 = __floats2half2_rn(sh[8 * u + 4][n], sh[8 * u + 5][n]);
            __half2 p3 = __floats2half2_rn(sh[8 * u + 6][n], sh[8 * u + 7][n]);
            uint4 v{*(uint32_t*)&p0, *(uint32_t*)&p1, *(uint32_t*)&p2, *(uint32_t*)&p3};
            *(uint4*)(dst + 8 * u) = v;
        }
        return;
    }

    // ---- P1: x fp32 -> fp16, 16 elems/thread (4 LDG.128 in flight) ----
    {
        const int blk = bid - K1_BLKS - P2_BLKS;   // 0..8191
        size_t i = ((size_t)blk * 256 + tid) * 16;
        float4 v0 = *(const float4*)(x + i);
        float4 v1 = *(const float4*)(x + i + 4);
        float4 v2 = *(const float4*)(x + i + 8);
        float4 v3 = *(const float4*)(x + i + 12);
        __half2 h0 = __floats2half2_rn(v0.x, v0.y);
        __half2 h1 = __floats2half2_rn(v0.z, v0.w);
        __half2 h2 = __floats2half2_rn(v1.x, v1.y);
        __half2 h3 = __floats2half2_rn(v1.z, v1.w);
        __half2 h4 = __floats2half2_rn(v2.x, v2.y);
        __half2 h5 = __floats2half2_rn(v2.z, v2.w);
        __half2 h6 = __floats2half2_rn(v3.x, v3.y);
        __half2 h7 = __floats2half2_rn(v3.z, v3.w);
        uint4 ua{*(uint32_t*)&h0, *(uint32_t*)&h1, *(uint32_t*)&h2, *(uint32_t*)&h3};
        uint4 ub{*(uint32_t*)&h4, *(uint32_t*)&h5, *(uint32_t*)&h6, *(uint32_t*)&h7};
        *(uint4*)(g_xf + i)     = ua;
        *(uint4*)(g_xf + i + 8) = ub;
    }
}

// ---------------------------------------------------------------------------
// K2: fused fp16 GEMM (fp16 acc), CTA tile 128x256, 8 warps of 64x64
// grid (NTREES, BATCH/128), 256 threads, 2-stage pipeline, 2 CTAs/SM
// stage = A[128][72] + B[256][72] fp16 = 55296 B; x2 = 110592
// ---------------------------------------------------------------------------
#define K2_AB  18432u
#define K2_STG 55296u
__global__ __launch_bounds__(256, 2) void k2_mma() {
    extern __shared__ char smem[];
    const uint32_t sb = smem_u32(smem);
    const int t    = blockIdx.x;
    const int row0 = blockIdx.y * 128;
    const int tid  = threadIdx.x;
    const int lane = tid & 31, wid = tid >> 5;
    const int wm = wid & 1, wn = wid >> 1;     // 2 x 4 warps: 64 rows x 64 cols

    const __half* pA = g_xf + (size_t)row0 * IN_DIM;
    const __half* pB = g_wf + (size_t)t * 256 * IN_DIM;

    const int arow = lane & 15, akof = (lane >> 4) * 8;
    uint32_t aoff[4];
#pragma unroll
    for (int mt = 0; mt < 4; mt++)
        aoff[mt] = ((wm * 64 + mt * 16 + arow) * 72 + akof) * 2;
    const int bg = lane >> 3;
    const int brow = ((bg >> 1) * 8) + (lane & 7);
    const int bkof = (bg & 1) * 8;
    uint32_t boff[4];
#pragma unroll
    for (int q = 0; q < 4; q++)
        boff[q] = ((wn * 64 + q * 16 + brow) * 72 + bkof) * 2;

    uint32_t acc[4][8][2];    // packed fp16 accumulators
#pragma unroll
    for (int a = 0; a < 4; a++)
#pragma unroll
        for (int b = 0; b < 8; b++) { acc[a][b][0] = 0u; acc[a][b][1] = 0u; }

    const int NC = IN_DIM / 64;   // 32 chunks of k=64

#define K2_LOAD(cc, stg) do {                                                     \
        const uint32_t st_ = sb + (uint32_t)(stg) * K2_STG;                       \
        const int k0_ = (cc) * 64;                                                \
        _Pragma("unroll")                                                         \
        for (int i_ = 0; i_ < 4; i_++) {                                          \
            int idx_ = tid + i_ * 256;                                            \
            int row_ = idx_ >> 3, ch_ = idx_ & 7;                                 \
            uint32_t d_ = st_ + row_ * 144 + ch_ * 16;                            \
            CPA(d_, (const char*)(pA + (size_t)row_ * IN_DIM + k0_ + ch_ * 8));   \
        }                                                                         \
        _Pragma("unroll")                                                         \
        for (int i_ = 0; i_ < 8; i_++) {                                          \
            int idx_ = tid + i_ * 256;                                            \
            int row_ = idx_ >> 3, ch_ = idx_ & 7;                                 \
            uint32_t d_ = st_ + K2_AB + row_ * 144 + ch_ * 16;                    \
            CPA(d_, (const char*)(pB + (size_t)row_ * IN_DIM + k0_ + ch_ * 8));   \
        }                                                                         \
    } while (0)

    K2_LOAD(0, 0); CPC();

    for (int c = 0; c < NC; c++) {
        CPW0();
        __syncthreads();
        if (c + 1 < NC) K2_LOAD(c + 1, (c + 1) & 1);
        CPC();
        const uint32_t st = sb + (uint32_t)(c & 1) * K2_STG;
#pragma unroll
        for (int ks = 0; ks < 4; ks++) {
            const uint32_t kb = ks * 32;      // 16 halves
            uint32_t a[4][4];
#pragma unroll
            for (int mt = 0; mt < 4; mt++)
                ldsm4(a[mt], st + aoff[mt] + kb);
#pragma unroll
            for (int q = 0; q < 4; q++) {
                uint32_t b[4];
                ldsm4(b, st + K2_AB + boff[q] + kb);
#pragma unroll
                for (int mt = 0; mt < 4; mt++) {
                    mma_f16h(acc[mt][2 * q],     a[mt], b + 0);
                    mma_f16h(acc[mt][2 * q + 1], a[mt], b + 2);
                }
            }
        }
    }
    __syncthreads();

    // ---------- fused epilogue: sigmoid -> P[128][264] fp16, tree products ---
    __half* P = (__half*)smem;
    const int cbase = wn * 64 + 2 * (lane & 3);
    const int rbase = wm * 64 + (lane >> 2);
#pragma unroll
    for (int mt = 0; mt < 4; mt++)
#pragma unroll
        for (int j = 0; j < 8; j++) {
            const int col = cbase + j * 8;
            const int row = rbase + mt * 16;
            float2 lo = __half22float2(*(__half2*)&acc[mt][j][0]);   // row
            float2 hi = __half22float2(*(__half2*)&acc[mt][j][1]);   // row+8
            __half2 slo = __floats2half2_rn(1.f / (1.f + __expf(-lo.x)),
                                            1.f / (1.f + __expf(-lo.y)));
            __half2 shi = __floats2half2_rn(1.f / (1.f + __expf(-hi.x)),
                                            1.f / (1.f + __expf(-hi.y)));
            *(__half2*)(P + row * 264 + col)       = slo;
            *(__half2*)(P + (row + 8) * 264 + col) = shi;
        }
    __syncthreads();

    const int m = tid;             // 0..255 leaves
    __nv_bfloat16* dst = g_prob + (size_t)row0 * KDIM2 + t * 256 + m;
    for (int r = 0; r < 128; r++) {
        const __half* Pr = P + r * 264;
        float prod = 1.f;
#pragma unroll
        for (int n = 0; n < 8; n++) {
            int node = (1 << n) - 1 + (m >> (8 - n));
            float p = __half2float(Pr[node]);
            prod *= ((m >> (7 - n)) & 1) ? (1.f - p) : p;
        }
        dst[(size_t)r * KDIM2] = __float2bfloat16(prod);
    }
#undef K2_LOAD
}

// ---------------------------------------------------------------------------
// K3: bf16 mma GEMM out[96x256] = prob[96x2560] * leafp^T, 8 warps of 48x64
// grid (4, 171), 256 threads, 2-stage pipeline (1 sync/chunk), 2 CTAs/SM
// stage = A[96][72] + B[256][72] bf16 = 50688 B; x2 = 101376
// ---------------------------------------------------------------------------
#define K3_AB  13824u
#define K3_STG 50688u
__global__ __launch_bounds__(256, 2) void k3_mma(float* __restrict__ out) {
    extern __shared__ char smem[];
    const uint32_t sb = smem_u32(smem);
    const int ct   = blockIdx.x;
    const int row0 = blockIdx.y * 96;
    const int tid  = threadIdx.x;
    const int lane = tid & 31, wid = tid >> 5;
    const int wm = wid & 1, wn = wid >> 1;    // 2 x 4 warps: 48 rows x 64 cols

    const __nv_bfloat16* pA = g_prob + (size_t)row0 * KDIM2;
    const __nv_bfloat16* pB = g_lpb + (size_t)(ct * 256) * KDIM2;

    const int arow = lane & 15, akof = (lane >> 4) * 8;
    uint32_t aoff[3];
#pragma unroll
    for (int mt = 0; mt < 3; mt++)
        aoff[mt] = ((wm * 48 + mt * 16 + arow) * 72 + akof) * 2;
    const int bg = lane >> 3;
    const int brow = ((bg >> 1) * 8) + (lane & 7);
    const int bkof = (bg & 1) * 8;
    uint32_t boff[4];
#pragma unroll
    for (int q = 0; q < 4; q++)
        boff[q] = ((wn * 64 + q * 16 + brow) * 72 + bkof) * 2;

    float acc[3][8][4];
#pragma unroll
    for (int a = 0; a < 3; a++)
#pragma unroll
        for (int b = 0; b < 8; b++)
#pragma unroll
            for (int c = 0; c < 4; c++) acc[a][b][c] = 0.f;

    const int NC = KDIM2 / 64;   // 40

#define K3_LOAD(cc, stg) do {                                                     \
        const uint32_t st_ = sb + (uint32_t)(stg) * K3_STG;                       \
        const int k0_ = (cc) * 64;                                                \
        _Pragma("unroll")                                                         \
        for (int i_ = 0; i_ < 3; i_++) {                                          \
            int idx_ = tid + i_ * 256;                                            \
            int row_ = idx_ >> 3, ch_ = idx_ & 7;                                 \
            uint32_t d_ = st_ + row_ * 144 + ch_ * 16;                            \
            CPA(d_, (const char*)(pA + (size_t)row_ * KDIM2 + k0_ + ch_ * 8));    \
        }                                                                         \
        _Pragma("unroll")                                                         \
        for (int i_ = 0; i_ < 8; i_++) {                                          \
            int idx_ = tid + i_ * 256;                                            \
            int row_ = idx_ >> 3, ch_ = idx_ & 7;                                 \
            uint32_t d_ = st_ + K3_AB + row_ * 144 + ch_ * 16;                    \
            CPA(d_, (const char*)(pB + (size_t)row_ * KDIM2 + k0_ + ch_ * 8));    \
        }                                                                         \
    } while (0)

    K3_LOAD(0, 0); CPC();

    for (int c = 0; c < NC; c++) {
        CPW0();
        __syncthreads();
        if (c + 1 < NC) K3_LOAD(c + 1, (c + 1) & 1);
        CPC();
        const uint32_t st = sb + (uint32_t)(c & 1) * K3_STG;
#pragma unroll
        for (int ks = 0; ks < 4; ks++) {
            const uint32_t kb = ks * 32;
            uint32_t a[3][4];
#pragma unroll
            for (int mt = 0; mt < 3; mt++)
                ldsm4(a[mt], st + aoff[mt] + kb);
#pragma unroll
            for (int q = 0; q < 4; q++) {
                uint32_t b[4];
                ldsm4(b, st + K3_AB + boff[q] + kb);
#pragma unroll
                for (int mt = 0; mt < 3; mt++) {
                    mma_bf16(acc[mt][2 * q],     a[mt], b + 0);
                    mma_bf16(acc[mt][2 * q + 1], a[mt], b + 2);
                }
            }
        }
    }

    const int cbase = ct * 256 + wn * 64 + 2 * (lane & 3);
    const int rbase = row0 + wm * 48 + (lane >> 2);
#pragma unroll
    for (int mt = 0; mt < 3; mt++)
#pragma unroll
        for (int j = 0; j < 8; j++) {
            int col = cbase + j * 8;
            int r0w = rbase + mt * 16;
            if (col + 1 < CLASSES) {
                if (r0w < BATCH)
                    *(float2*)(out + (size_t)r0w * CLASSES + col) = make_float2(acc[mt][j][0], acc[mt][j][1]);
                if (r0w + 8 < BATCH)
                    *(float2*)(out + (size_t)(r0w + 8) * CLASSES + col) = make_float2(acc[mt][j][2], acc[mt][j][3]);
            } else if (col < CLASSES) {
                if (r0w < BATCH)     out[(size_t)r0w * CLASSES + col] = acc[mt][j][0];
                if (r0w + 8 < BATCH) out[(size_t)(r0w + 8) * CLASSES + col] = acc[mt][j][2];
            }
        }
#undef K3_LOAD
}

// ---------------------------------------------------------------------------
extern "C" void kernel_launch(void* const* d_in, const int* in_sizes, int n_in,
                              void* d_out, int out_size) {
    const float* x = nullptr;
    const float* wd = nullptr;
    const float* wl = nullptr;
    for (int i = 0; i < n_in; i++) {
        if (in_sizes[i] == BATCH * IN_DIM)              x = (const float*)d_in[i];
        else if (in_sizes[i] == NTREES * IN_DIM * NDEC) wd = (const float*)d_in[i];
        else if (in_sizes[i] == NTREES * 512 * CLASSES) wl = (const float*)d_in[i];
    }
    float* out = (float*)d_out;

    cudaFuncSetAttribute(k2_mma, cudaFuncAttributeMaxDynamicSharedMemorySize, 2 * K2_STG);
    cudaFuncSetAttribute(k3_mma, cudaFuncAttributeMaxDynamicSharedMemorySize, 2 * K3_STG);

    k0_prep<<<K1_BLKS + P2_BLKS + P1_BLKS, 256>>>(x, wd, wl);
    k2_mma<<<dim3(NTREES, BATCH / 128), 256, 2 * K2_STG>>>();
    k3_mma<<<dim3(4, (BATCH + 95) / 96), 256, 2 * K3_STG>>>(out);
}

// round 15
// speedup vs baseline: 1.0370x; 1.0315x over previous
#include <cuda_runtime.h>
#include <cuda_bf16.h>
#include <cuda_fp16.h>
#include <cstdint>

#define BATCH   16384
#define BATCH_P 16416         // padded rows for K3's 96-row tiles
#define IN_DIM  2048
#define NTREES  10
#define NDEC    255
#define CLASSES 1000
#define KDIM2   2560          // NTREES * 256
#define NPAD    1024          // padded class rows for K3 B matrix

// ---------------- device scratch ----------------
__device__ __half         g_xf[(size_t)BATCH * IN_DIM];          // x in fp16
__device__ __half         g_wf[(size_t)NTREES * 256 * IN_DIM];   // w fp16, [t][n][k]
__device__ __nv_bfloat16  g_lpb[(size_t)NPAD * KDIM2];           // [class][k] K-major
__device__ __nv_bfloat16  g_prob[(size_t)BATCH_P * KDIM2];       // padded (rows>=16384 stay 0)

// ---------------- PTX helpers ----------------
__device__ __forceinline__ uint32_t smem_u32(const void* p) {
    uint32_t a;
    asm("{ .reg .u64 t; cvta.to.shared.u64 t, %1; cvt.u32.u64 %0, t; }" : "=r"(a) : "l"(p));
    return a;
}
#define CPA(dst, src) asm volatile("cp.async.cg.shared.global [%0], [%1], 16;" :: "r"(dst), "l"(src))
#define CPC()  asm volatile("cp.async.commit_group;" ::: "memory")
#define CPW0() asm volatile("cp.async.wait_group 0;" ::: "memory")

__device__ __forceinline__ void ldsm4(uint32_t* r, uint32_t addr) {
    asm volatile("ldmatrix.sync.aligned.m8n8.x4.shared.b16 {%0,%1,%2,%3}, [%4];"
                 : "=r"(r[0]), "=r"(r[1]), "=r"(r[2]), "=r"(r[3]) : "r"(addr));
}
__device__ __forceinline__ void mma_bf16(float* c, const uint32_t* a, const uint32_t* b) {
    asm volatile("mma.sync.aligned.m16n8k16.row.col.f32.bf16.bf16.f32 "
                 "{%0,%1,%2,%3}, {%4,%5,%6,%7}, {%8,%9}, {%0,%1,%2,%3};"
                 : "+f"(c[0]), "+f"(c[1]), "+f"(c[2]), "+f"(c[3])
                 : "r"(a[0]), "r"(a[1]), "r"(a[2]), "r"(a[3]), "r"(b[0]), "r"(b[1]));
}
// fp16 accumulate variant: C/D = 2 packed-half regs
__device__ __forceinline__ void mma_f16h(uint32_t* c, const uint32_t* a, const uint32_t* b) {
    asm volatile("mma.sync.aligned.m16n8k16.row.col.f16.f16.f16.f16 "
                 "{%0,%1}, {%2,%3,%4,%5}, {%6,%7}, {%0,%1};"
                 : "+r"(c[0]), "+r"(c[1])
                 : "r"(a[0]), "r"(a[1]), "r"(a[2]), "r"(a[3]), "r"(b[0]), "r"(b[1]));
}

// ---------------------------------------------------------------------------
// K0: fused prelude — K1 (softmax, 4 leaf-pairs/block, coalesced writes),
//     then P2 (w transpose), then P1 (x->fp16 stream)
// grid = 640 + 640 + 8192 = 9472 blocks, 256 threads
// ---------------------------------------------------------------------------
#define K1_BLKS 640
#define P2_BLKS 640
#define P1_BLKS 8192          // 16 floats per thread
__global__ __launch_bounds__(256) void k0_prep(const float* __restrict__ x,
                                               const float* __restrict__ wd,
                                               const float* __restrict__ wl) {
    const int bid = blockIdx.x;
    const int tid = threadIdx.x;

    if (bid < K1_BLKS) {
        // ---- K1: paired softmax, block = (tree, 4 leaf-pairs = 8 wl rows) ----
        __shared__ float s[8 * CLASSES];     // 32 KB, 8 contiguous rows
        __shared__ float Ms[8], Is[8];
        const int t  = bid >> 6;             // 0..9
        const int m0 = (bid & 63) * 4;       // leaf-pair base, 0..252
        const int lane = tid & 31, w = tid >> 5;   // 8 warps

        // coalesced load: 8 contiguous rows (8000 floats)
        const float* r0 = wl + (size_t)(t * 512 + 2 * m0) * CLASSES;
        for (int idx = tid; idx < 8 * CLASSES; idx += 256) s[idx] = r0[idx];
        __syncthreads();

        // warp w reduces row w: max then sum of exp
        {
            const float* row = s + w * CLASSES;
            float mx = -1e30f;
            for (int i = lane; i < CLASSES; i += 32) mx = fmaxf(mx, row[i]);
#pragma unroll
            for (int o = 16; o > 0; o >>= 1) mx = fmaxf(mx, __shfl_xor_sync(0xffffffffu, mx, o));
            float sm = 0.f;
            for (int i = lane; i < CLASSES; i += 32) sm += __expf(row[i] - mx);
#pragma unroll
            for (int o = 16; o > 0; o >>= 1) sm += __shfl_xor_sync(0xffffffffu, sm, o);
            if (lane == 0) { Ms[w] = mx; Is[w] = 1.f / sm; }
        }
        __syncthreads();

        // write phase: j = leaf-pair within block (4 consecutive m -> coalesced)
        const int j  = tid & 3;
        const int ib = tid >> 2;             // 64 classes per pass
        const float sc = 1.f / (float)NTREES;
        const float M0 = Ms[2 * j],     I0 = Is[2 * j];
        const float M1 = Ms[2 * j + 1], I1 = Is[2 * j + 1];
        const float* row0 = s + (2 * j) * CLASSES;
        const float* row1 = s + (2 * j + 1) * CLASSES;
        __nv_bfloat16* dst = g_lpb + t * 256 + m0 + j;
#pragma unroll
        for (int p = 0; p < 16; p++) {
            int i = ib + p * 64;
            if (i < CLASSES) {
                float e0 = __expf(row0[i] - M0) * I0;
                float e1 = __expf(row1[i] - M1) * I1;
                dst[(size_t)i * KDIM2] = __float2bfloat16((e0 + e1) * sc);
            }
        }
        return;
    }

    if (bid < K1_BLKS + P2_BLKS) {
        // ---- P2: w_d [t][k][255] -> g_wf [t][n][k] fp16 K-major ----
        __shared__ float sh[32][257];
        const int blk = bid - K1_BLKS;       // 0..639
        const int t = blk >> 6;              // 0..9
        const int k0 = (blk & 63) * 32;
        const int n = tid;
        const float* wp = wd + (size_t)t * IN_DIM * NDEC;
#pragma unroll
        for (int kk = 0; kk < 32; kk++)
            sh[kk][n] = (n < NDEC) ? wp[(size_t)(k0 + kk) * NDEC + n] : 0.f;
        __syncthreads();
        __half* dst = g_wf + ((size_t)t * 256 + n) * IN_DIM + k0;
#pragma unroll
        for (int u = 0; u < 4; u++) {
            __half2 p0 = __floats2half2_rn(sh[8 * u + 0][n], sh[8 * u + 1][n]);
            __half2 p1 = __floats2half2_rn(sh[8 * u + 2][n], sh[8 * u + 3][n]);
            __half2 p2 = __floats2half2_rn(sh[8 * u + 4][n], sh[8 * u + 5][n]);
            __half2 p3 = __floats2half2_rn(sh[8 * u + 6][n], sh[8 * u + 7][n]);
            uint4 v{*(uint32_t*)&p0, *(uint32_t*)&p1, *(uint32_t*)&p2, *(uint32_t*)&p3};
            *(uint4*)(dst + 8 * u) = v;
        }
        return;
    }

    // ---- P1: x fp32 -> fp16, 16 elems/thread (4 LDG.128 in flight) ----
    {
        const int blk = bid - K1_BLKS - P2_BLKS;   // 0..8191
        size_t i = ((size_t)blk * 256 + tid) * 16;
        float4 v0 = *(const float4*)(x + i);
        float4 v1 = *(const float4*)(x + i + 4);
        float4 v2 = *(const float4*)(x + i + 8);
        float4 v3 = *(const float4*)(x + i + 12);
        __half2 h0 = __floats2half2_rn(v0.x, v0.y);
        __half2 h1 = __floats2half2_rn(v0.z, v0.w);
        __half2 h2 = __floats2half2_rn(v1.x, v1.y);
        __half2 h3 = __floats2half2_rn(v1.z, v1.w);
        __half2 h4 = __floats2half2_rn(v2.x, v2.y);
        __half2 h5 = __floats2half2_rn(v2.z, v2.w);
        __half2 h6 = __floats2half2_rn(v3.x, v3.y);
        __half2 h7 = __floats2half2_rn(v3.z, v3.w);
        uint4 ua{*(uint32_t*)&h0, *(uint32_t*)&h1, *(uint32_t*)&h2, *(uint32_t*)&h3};
        uint4 ub{*(uint32_t*)&h4, *(uint32_t*)&h5, *(uint32_t*)&h6, *(uint32_t*)&h7};
        *(uint4*)(g_xf + i)     = ua;
        *(uint4*)(g_xf + i + 8) = ub;
    }
}

// ---------------------------------------------------------------------------
// K2: fused fp16 GEMM (fp16 acc), CTA tile 128x256, 8 warps of 64x64
// grid (NTREES, BATCH/128), 256 threads, 2-stage pipeline, 2 CTAs/SM
// stage = A[128][72] + B[256][72] fp16 = 55296 B; x2 = 110592
// ---------------------------------------------------------------------------
#define K2_AB  18432u
#define K2_STG 55296u
__global__ __launch_bounds__(256, 2) void k2_mma() {
    extern __shared__ char smem[];
    const uint32_t sb = smem_u32(smem);
    const int t    = blockIdx.x;
    const int row0 = blockIdx.y * 128;
    const int tid  = threadIdx.x;
    const int lane = tid & 31, wid = tid >> 5;
    const int wm = wid & 1, wn = wid >> 1;     // 2 x 4 warps: 64 rows x 64 cols

    const __half* pA = g_xf + (size_t)row0 * IN_DIM;
    const __half* pB = g_wf + (size_t)t * 256 * IN_DIM;

    const int arow = lane & 15, akof = (lane >> 4) * 8;
    uint32_t aoff[4];
#pragma unroll
    for (int mt = 0; mt < 4; mt++)
        aoff[mt] = ((wm * 64 + mt * 16 + arow) * 72 + akof) * 2;
    const int bg = lane >> 3;
    const int brow = ((bg >> 1) * 8) + (lane & 7);
    const int bkof = (bg & 1) * 8;
    uint32_t boff[4];
#pragma unroll
    for (int q = 0; q < 4; q++)
        boff[q] = ((wn * 64 + q * 16 + brow) * 72 + bkof) * 2;

    uint32_t acc[4][8][2];    // packed fp16 accumulators
#pragma unroll
    for (int a = 0; a < 4; a++)
#pragma unroll
        for (int b = 0; b < 8; b++) { acc[a][b][0] = 0u; acc[a][b][1] = 0u; }

    const int NC = IN_DIM / 64;   // 32 chunks of k=64

#define K2_LOAD(cc, stg) do {                                                     \
        const uint32_t st_ = sb + (uint32_t)(stg) * K2_STG;                       \
        const int k0_ = (cc) * 64;                                                \
        _Pragma("unroll")                                                         \
        for (int i_ = 0; i_ < 4; i_++) {                                          \
            int idx_ = tid + i_ * 256;                                            \
            int row_ = idx_ >> 3, ch_ = idx_ & 7;                                 \
            uint32_t d_ = st_ + row_ * 144 + ch_ * 16;                            \
            CPA(d_, (const char*)(pA + (size_t)row_ * IN_DIM + k0_ + ch_ * 8));   \
        }                                                                         \
        _Pragma("unroll")                                                         \
        for (int i_ = 0; i_ < 8; i_++) {                                          \
            int idx_ = tid + i_ * 256;                                            \
            int row_ = idx_ >> 3, ch_ = idx_ & 7;                                 \
            uint32_t d_ = st_ + K2_AB + row_ * 144 + ch_ * 16;                    \
            CPA(d_, (const char*)(pB + (size_t)row_ * IN_DIM + k0_ + ch_ * 8));   \
        }                                                                         \
    } while (0)

    K2_LOAD(0, 0); CPC();

    for (int c = 0; c < NC; c++) {
        CPW0();
        __syncthreads();
        if (c + 1 < NC) K2_LOAD(c + 1, (c + 1) & 1);
        CPC();
        const uint32_t st = sb + (uint32_t)(c & 1) * K2_STG;
#pragma unroll
        for (int ks = 0; ks < 4; ks++) {
            const uint32_t kb = ks * 32;      // 16 halves
            uint32_t a[4][4];
#pragma unroll
            for (int mt = 0; mt < 4; mt++)
                ldsm4(a[mt], st + aoff[mt] + kb);
#pragma unroll
            for (int q = 0; q < 4; q++) {
                uint32_t b[4];
                ldsm4(b, st + K2_AB + boff[q] + kb);
#pragma unroll
                for (int mt = 0; mt < 4; mt++) {
                    mma_f16h(acc[mt][2 * q],     a[mt], b + 0);
                    mma_f16h(acc[mt][2 * q + 1], a[mt], b + 2);
                }
            }
        }
    }
    __syncthreads();

    // ---------- fused epilogue: sigmoid -> P[128][264] fp16, tree products ---
    __half* P = (__half*)smem;
    const int cbase = wn * 64 + 2 * (lane & 3);
    const int rbase = wm * 64 + (lane >> 2);
#pragma unroll
    for (int mt = 0; mt < 4; mt++)
#pragma unroll
        for (int j = 0; j < 8; j++) {
            const int col = cbase + j * 8;
            const int row = rbase + mt * 16;
            float2 lo = __half22float2(*(__half2*)&acc[mt][j][0]);   // row
            float2 hi = __half22float2(*(__half2*)&acc[mt][j][1]);   // row+8
            __half2 slo = __floats2half2_rn(1.f / (1.f + __expf(-lo.x)),
                                            1.f / (1.f + __expf(-lo.y)));
            __half2 shi = __floats2half2_rn(1.f / (1.f + __expf(-hi.x)),
                                            1.f / (1.f + __expf(-hi.y)));
            *(__half2*)(P + row * 264 + col)       = slo;
            *(__half2*)(P + (row + 8) * 264 + col) = shi;
        }
    __syncthreads();

    const int m = tid;             // 0..255 leaves
    __nv_bfloat16* dst = g_prob + (size_t)row0 * KDIM2 + t * 256 + m;
    for (int r = 0; r < 128; r++) {
        const __half* Pr = P + r * 264;
        float prod = 1.f;
#pragma unroll
        for (int n = 0; n < 8; n++) {
            int node = (1 << n) - 1 + (m >> (8 - n));
            float p = __half2float(Pr[node]);
            prod *= ((m >> (7 - n)) & 1) ? (1.f - p) : p;
        }
        dst[(size_t)r * KDIM2] = __float2bfloat16(prod);
    }
#undef K2_LOAD
}

// ---------------------------------------------------------------------------
// K3: bf16 mma GEMM out[96x256] = prob[96x2560] * leafp^T, 8 warps of 48x64
// grid (4, 171), 256 threads, 2-stage pipeline (1 sync/chunk), 2 CTAs/SM
// stage = A[96][72] + B[256][72] bf16 = 50688 B; x2 = 101376
// ---------------------------------------------------------------------------
#define K3_AB  13824u
#define K3_STG 50688u
__global__ __launch_bounds__(256, 2) void k3_mma(float* __restrict__ out) {
    extern __shared__ char smem[];
    const uint32_t sb = smem_u32(smem);
    const int ct   = blockIdx.x;
    const int row0 = blockIdx.y * 96;
    const int tid  = threadIdx.x;
    const int lane = tid & 31, wid = tid >> 5;
    const int wm = wid & 1, wn = wid >> 1;    // 2 x 4 warps: 48 rows x 64 cols

    const __nv_bfloat16* pA = g_prob + (size_t)row0 * KDIM2;
    const __nv_bfloat16* pB = g_lpb + (size_t)(ct * 256) * KDIM2;

    const int arow = lane & 15, akof = (lane >> 4) * 8;
    uint32_t aoff[3];
#pragma unroll
    for (int mt = 0; mt < 3; mt++)
        aoff[mt] = ((wm * 48 + mt * 16 + arow) * 72 + akof) * 2;
    const int bg = lane >> 3;
    const int brow = ((bg >> 1) * 8) + (lane & 7);
    const int bkof = (bg & 1) * 8;
    uint32_t boff[4];
#pragma unroll
    for (int q = 0; q < 4; q++)
        boff[q] = ((wn * 64 + q * 16 + brow) * 72 + bkof) * 2;

    float acc[3][8][4];
#pragma unroll
    for (int a = 0; a < 3; a++)
#pragma unroll
        for (int b = 0; b < 8; b++)
#pragma unroll
            for (int c = 0; c < 4; c++) acc[a][b][c] = 0.f;

    const int NC = KDIM2 / 64;   // 40

#define K3_LOAD(cc, stg) do {                                                     \
        const uint32_t st_ = sb + (uint32_t)(stg) * K3_STG;                       \
        const int k0_ = (cc) * 64;                                                \
        _Pragma("unroll")                                                         \
        for (int i_ = 0; i_ < 3; i_++) {                                          \
            int idx_ = tid + i_ * 256;                                            \
            int row_ = idx_ >> 3, ch_ = idx_ & 7;                                 \
            uint32_t d_ = st_ + row_ * 144 + ch_ * 16;                            \
            CPA(d_, (const char*)(pA + (size_t)row_ * KDIM2 + k0_ + ch_ * 8));    \
        }                                                                         \
        _Pragma("unroll")                                                         \
        for (int i_ = 0; i_ < 8; i_++) {                                          \
            int idx_ = tid + i_ * 256;                                            \
            int row_ = idx_ >> 3, ch_ = idx_ & 7;                                 \
            uint32_t d_ = st_ + K3_AB + row_ * 144 + ch_ * 16;                    \
            CPA(d_, (const char*)(pB + (size_t)row_ * KDIM2 + k0_ + ch_ * 8));    \
        }                                                                         \
    } while (0)

    K3_LOAD(0, 0); CPC();

    for (int c = 0; c < NC; c++) {
        CPW0();
        __syncthreads();
        if (c + 1 < NC) K3_LOAD(c + 1, (c + 1) & 1);
        CPC();
        const uint32_t st = sb + (uint32_t)(c & 1) * K3_STG;
#pragma unroll
        for (int ks = 0; ks < 4; ks++) {
            const uint32_t kb = ks * 32;
            uint32_t a[3][4];
#pragma unroll
            for (int mt = 0; mt < 3; mt++)
                ldsm4(a[mt], st + aoff[mt] + kb);
#pragma unroll
            for (int q = 0; q < 4; q++) {
                uint32_t b[4];
                ldsm4(b, st + K3_AB + boff[q] + kb);
#pragma unroll
                for (int mt = 0; mt < 3; mt++) {
                    mma_bf16(acc[mt][2 * q],     a[mt], b + 0);
                    mma_bf16(acc[mt][2 * q + 1], a[mt], b + 2);
                }
            }
        }
    }

    const int cbase = ct * 256 + wn * 64 + 2 * (lane & 3);
    const int rbase = row0 + wm * 48 + (lane >> 2);
#pragma unroll
    for (int mt = 0; mt < 3; mt++)
#pragma unroll
        for (int j = 0; j < 8; j++) {
            int col = cbase + j * 8;
            int r0w = rbase + mt * 16;
            if (col + 1 < CLASSES) {
                if (r0w < BATCH)
                    *(float2*)(out + (size_t)r0w * CLASSES + col) = make_float2(acc[mt][j][0], acc[mt][j][1]);
                if (r0w + 8 < BATCH)
                    *(float2*)(out + (size_t)(r0w + 8) * CLASSES + col) = make_float2(acc[mt][j][2], acc[mt][j][3]);
            } else if (col < CLASSES) {
                if (r0w < BATCH)     out[(size_t)r0w * CLASSES + col] = acc[mt][j][0];
                if (r0w + 8 < BATCH) out[(size_t)(r0w + 8) * CLASSES + col] = acc[mt][j][2];
            }
        }
#undef K3_LOAD
}

// ---------------------------------------------------------------------------
extern "C" void kernel_launch(void* const* d_in, const int* in_sizes, int n_in,
                              void* d_out, int out_size) {
    const float* x = nullptr;
    const float* wd = nullptr;
    const float* wl = nullptr;
    for (int i = 0; i < n_in; i++) {
        if (in_sizes[i] == BATCH * IN_DIM)              x = (const float*)d_in[i];
        else if (in_sizes[i] == NTREES * IN_DIM * NDEC) wd = (const float*)d_in[i];
        else if (in_sizes[i] == NTREES * 512 * CLASSES) wl = (const float*)d_in[i];
    }
    float* out = (float*)d_out;

    cudaFuncSetAttribute(k2_mma, cudaFuncAttributeMaxDynamicSharedMemorySize, 2 * K2_STG);
    cudaFuncSetAttribute(k3_mma, cudaFuncAttributeMaxDynamicSharedMemorySize, 2 * K3_STG);

    k0_prep<<<K1_BLKS + P2_BLKS + P1_BLKS, 256>>>(x, wd, wl);
    k2_mma<<<dim3(NTREES, BATCH / 128), 256, 2 * K2_STG>>>();
    k3_mma<<<dim3(4, (BATCH + 95) / 96), 256, 2 * K3_STG>>>(out);
}

// round 16
// speedup vs baseline: 1.0478x; 1.0104x over previous
#include <cuda_runtime.h>
#include <cuda_bf16.h>
#include <cuda_fp16.h>
#include <cstdint>

#define BATCH   16384
#define BATCH_P 16416         // padded rows for K3's 96-row tiles
#define IN_DIM  2048
#define NTREES  10
#define NDEC    255
#define CLASSES 1000
#define KDIM2   2560          // NTREES * 256
#define NPAD    1024          // padded class rows for K3 B matrix

// ---------------- device scratch ----------------
__device__ __half         g_xf[(size_t)BATCH * IN_DIM];          // x in fp16
__device__ __half         g_wf[(size_t)NTREES * 256 * IN_DIM];   // w fp16, [t][n][k]
__device__ __nv_bfloat16  g_lpb[(size_t)NPAD * KDIM2];           // [class][k] K-major
__device__ __nv_bfloat16  g_prob[(size_t)BATCH_P * KDIM2];       // padded (rows>=16384 stay 0)

// ---------------- PTX helpers ----------------
__device__ __forceinline__ uint32_t smem_u32(const void* p) {
    uint32_t a;
    asm("{ .reg .u64 t; cvta.to.shared.u64 t, %1; cvt.u32.u64 %0, t; }" : "=r"(a) : "l"(p));
    return a;
}
#define CPA(dst, src) asm volatile("cp.async.cg.shared.global [%0], [%1], 16;" :: "r"(dst), "l"(src))
#define CPC()  asm volatile("cp.async.commit_group;" ::: "memory")
#define CPW0() asm volatile("cp.async.wait_group 0;" ::: "memory")

__device__ __forceinline__ void ldsm4(uint32_t* r, uint32_t addr) {
    asm volatile("ldmatrix.sync.aligned.m8n8.x4.shared.b16 {%0,%1,%2,%3}, [%4];"
                 : "=r"(r[0]), "=r"(r[1]), "=r"(r[2]), "=r"(r[3]) : "r"(addr));
}
__device__ __forceinline__ void mma_bf16(float* c, const uint32_t* a, const uint32_t* b) {
    asm volatile("mma.sync.aligned.m16n8k16.row.col.f32.bf16.bf16.f32 "
                 "{%0,%1,%2,%3}, {%4,%5,%6,%7}, {%8,%9}, {%0,%1,%2,%3};"
                 : "+f"(c[0]), "+f"(c[1]), "+f"(c[2]), "+f"(c[3])
                 : "r"(a[0]), "r"(a[1]), "r"(a[2]), "r"(a[3]), "r"(b[0]), "r"(b[1]));
}
// fp16 accumulate variant: C/D = 2 packed-half regs
__device__ __forceinline__ void mma_f16h(uint32_t* c, const uint32_t* a, const uint32_t* b) {
    asm volatile("mma.sync.aligned.m16n8k16.row.col.f16.f16.f16.f16 "
                 "{%0,%1}, {%2,%3,%4,%5}, {%6,%7}, {%0,%1};"
                 : "+r"(c[0]), "+r"(c[1])
                 : "r"(a[0]), "r"(a[1]), "r"(a[2]), "r"(a[3]), "r"(b[0]), "r"(b[1]));
}

// ---------------------------------------------------------------------------
// K0: fused prelude — K1 (softmax, gmem-direct, coalesced writes),
//     P2 (w transpose, 16 k-rows/block), P1 (x->fp16 stream, 8 elems/thread)
// grid = 640 + 1280 + 16384 = 18304 blocks, 256 threads
// ---------------------------------------------------------------------------
#define K1_BLKS 640
#define P2_BLKS 1280
#define P1_BLKS 16384
__global__ __launch_bounds__(256) void k0_prep(const float* __restrict__ x,
                                               const float* __restrict__ wd,
                                               const float* __restrict__ wl) {
    const int bid = blockIdx.x;
    const int tid = threadIdx.x;

    if (bid < K1_BLKS) {
        // ---- K1: paired softmax, block = (tree, 4 leaf-pairs = 8 wl rows),
        //      gmem-direct (L2-hot), warp-shfl reductions, coalesced writes ----
        __shared__ float Ms[8], Is[8];
        const int t  = bid >> 6;             // 0..9
        const int m0 = (bid & 63) * 4;       // leaf-pair base, 0..252
        const int lane = tid & 31, w = tid >> 5;   // 8 warps, warp w owns row w

        const float* r0 = wl + (size_t)(t * 512 + 2 * m0) * CLASSES;
        {
            const float* row = r0 + (size_t)w * CLASSES;
            float mx = -1e30f;
            for (int i = lane; i < CLASSES; i += 32) mx = fmaxf(mx, row[i]);
#pragma unroll
            for (int o = 16; o > 0; o >>= 1) mx = fmaxf(mx, __shfl_xor_sync(0xffffffffu, mx, o));
            float sm = 0.f;
            for (int i = lane; i < CLASSES; i += 32) sm += __expf(row[i] - mx);
#pragma unroll
            for (int o = 16; o > 0; o >>= 1) sm += __shfl_xor_sync(0xffffffffu, sm, o);
            if (lane == 0) { Ms[w] = mx; Is[w] = 1.f / sm; }
        }
        __syncthreads();

        // write phase: j = leaf-pair within block (4 consecutive m -> coalesced)
        const int j  = tid & 3;
        const int ib = tid >> 2;             // 64 classes per pass
        const float sc = 1.f / (float)NTREES;
        const float M0 = Ms[2 * j],     I0 = Is[2 * j];
        const float M1 = Ms[2 * j + 1], I1 = Is[2 * j + 1];
        const float* row0 = r0 + (size_t)(2 * j) * CLASSES;
        const float* row1 = r0 + (size_t)(2 * j + 1) * CLASSES;
        __nv_bfloat16* dst = g_lpb + t * 256 + m0 + j;
#pragma unroll
        for (int p = 0; p < 16; p++) {
            int i = ib + p * 64;
            if (i < CLASSES) {
                float e0 = __expf(row0[i] - M0) * I0;
                float e1 = __expf(row1[i] - M1) * I1;
                dst[(size_t)i * KDIM2] = __float2bfloat16((e0 + e1) * sc);
            }
        }
        return;
    }

    if (bid < K1_BLKS + P2_BLKS) {
        // ---- P2: w_d [t][k][255] -> g_wf [t][n][k] fp16 K-major, 16 k-rows ----
        __shared__ float sh[16][257];
        const int blk = bid - K1_BLKS;       // 0..1279
        const int t = blk >> 7;              // 0..9
        const int k0 = (blk & 127) * 16;
        const int n = tid;
        const float* wp = wd + (size_t)t * IN_DIM * NDEC;
#pragma unroll
        for (int kk = 0; kk < 16; kk++)
            sh[kk][n] = (n < NDEC) ? wp[(size_t)(k0 + kk) * NDEC + n] : 0.f;
        __syncthreads();
        __half* dst = g_wf + ((size_t)t * 256 + n) * IN_DIM + k0;
#pragma unroll
        for (int u = 0; u < 2; u++) {
            __half2 p0 = __floats2half2_rn(sh[8 * u + 0][n], sh[8 * u + 1][n]);
            __half2 p1 = __floats2half2_rn(sh[8 * u + 2][n], sh[8 * u + 3][n]);
            __half2 p2 = __floats2half2_rn(sh[8 * u + 4][n], sh[8 * u + 5][n]);
            __half2 p3 = __floats2half2_rn(sh[8 * u + 6][n], sh[8 * u + 7][n]);
            uint4 v{*(uint32_t*)&p0, *(uint32_t*)&p1, *(uint32_t*)&p2, *(uint32_t*)&p3};
            *(uint4*)(dst + 8 * u) = v;
        }
        return;
    }

    // ---- P1: x fp32 -> fp16, 8 elems/thread ----
    {
        const int blk = bid - K1_BLKS - P2_BLKS;   // 0..16383
        size_t i = ((size_t)blk * 256 + tid) * 8;
        float4 v0 = *(const float4*)(x + i);
        float4 v1 = *(const float4*)(x + i + 4);
        __half2 h0 = __floats2half2_rn(v0.x, v0.y);
        __half2 h1 = __floats2half2_rn(v0.z, v0.w);
        __half2 h2 = __floats2half2_rn(v1.x, v1.y);
        __half2 h3 = __floats2half2_rn(v1.z, v1.w);
        uint4 u{*(uint32_t*)&h0, *(uint32_t*)&h1, *(uint32_t*)&h2, *(uint32_t*)&h3};
        *(uint4*)(g_xf + i) = u;
    }
}

// ---------------------------------------------------------------------------
// K2: fused fp16 GEMM (fp16 acc), CTA tile 128x256, 8 warps of 64x64
// grid (NTREES, BATCH/128), 256 threads, 2-stage pipeline, 2 CTAs/SM
// stage = A[128][72] + B[256][72] fp16 = 55296 B; x2 = 110592
// ---------------------------------------------------------------------------
#define K2_AB  18432u
#define K2_STG 55296u
__global__ __launch_bounds__(256, 2) void k2_mma() {
    extern __shared__ char smem[];
    const uint32_t sb = smem_u32(smem);
    const int t    = blockIdx.x;
    const int row0 = blockIdx.y * 128;
    const int tid  = threadIdx.x;
    const int lane = tid & 31, wid = tid >> 5;
    const int wm = wid & 1, wn = wid >> 1;     // 2 x 4 warps: 64 rows x 64 cols

    const __half* pA = g_xf + (size_t)row0 * IN_DIM;
    const __half* pB = g_wf + (size_t)t * 256 * IN_DIM;

    const int arow = lane & 15, akof = (lane >> 4) * 8;
    uint32_t aoff[4];
#pragma unroll
    for (int mt = 0; mt < 4; mt++)
        aoff[mt] = ((wm * 64 + mt * 16 + arow) * 72 + akof) * 2;
    const int bg = lane >> 3;
    const int brow = ((bg >> 1) * 8) + (lane & 7);
    const int bkof = (bg & 1) * 8;
    uint32_t boff[4];
#pragma unroll
    for (int q = 0; q < 4; q++)
        boff[q] = ((wn * 64 + q * 16 + brow) * 72 + bkof) * 2;

    uint32_t acc[4][8][2];    // packed fp16 accumulators
#pragma unroll
    for (int a = 0; a < 4; a++)
#pragma unroll
        for (int b = 0; b < 8; b++) { acc[a][b][0] = 0u; acc[a][b][1] = 0u; }

    const int NC = IN_DIM / 64;   // 32 chunks of k=64

#define K2_LOAD(cc, stg) do {                                                     \
        const uint32_t st_ = sb + (uint32_t)(stg) * K2_STG;                       \
        const int k0_ = (cc) * 64;                                                \
        _Pragma("unroll")                                                         \
        for (int i_ = 0; i_ < 4; i_++) {                                          \
            int idx_ = tid + i_ * 256;                                            \
            int row_ = idx_ >> 3, ch_ = idx_ & 7;                                 \
            uint32_t d_ = st_ + row_ * 144 + ch_ * 16;                            \
            CPA(d_, (const char*)(pA + (size_t)row_ * IN_DIM + k0_ + ch_ * 8));   \
        }                                                                         \
        _Pragma("unroll")                                                         \
        for (int i_ = 0; i_ < 8; i_++) {                                          \
            int idx_ = tid + i_ * 256;                                            \
            int row_ = idx_ >> 3, ch_ = idx_ & 7;                                 \
            uint32_t d_ = st_ + K2_AB + row_ * 144 + ch_ * 16;                    \
            CPA(d_, (const char*)(pB + (size_t)row_ * IN_DIM + k0_ + ch_ * 8));   \
        }                                                                         \
    } while (0)

    K2_LOAD(0, 0); CPC();

    for (int c = 0; c < NC; c++) {
        CPW0();
        __syncthreads();
        if (c + 1 < NC) K2_LOAD(c + 1, (c + 1) & 1);
        CPC();
        const uint32_t st = sb + (uint32_t)(c & 1) * K2_STG;
#pragma unroll
        for (int ks = 0; ks < 4; ks++) {
            const uint32_t kb = ks * 32;      // 16 halves
            uint32_t a[4][4];
#pragma unroll
            for (int mt = 0; mt < 4; mt++)
                ldsm4(a[mt], st + aoff[mt] + kb);
#pragma unroll
            for (int q = 0; q < 4; q++) {
                uint32_t b[4];
                ldsm4(b, st + K2_AB + boff[q] + kb);
#pragma unroll
                for (int mt = 0; mt < 4; mt++) {
                    mma_f16h(acc[mt][2 * q],     a[mt], b + 0);
                    mma_f16h(acc[mt][2 * q + 1], a[mt], b + 2);
                }
            }
        }
    }
    __syncthreads();

    // ---------- fused epilogue: sigmoid -> P[128][264] fp16, tree products ---
    __half* P = (__half*)smem;
    const int cbase = wn * 64 + 2 * (lane & 3);
    const int rbase = wm * 64 + (lane >> 2);
#pragma unroll
    for (int mt = 0; mt < 4; mt++)
#pragma unroll
        for (int j = 0; j < 8; j++) {
            const int col = cbase + j * 8;
            const int row = rbase + mt * 16;
            float2 lo = __half22float2(*(__half2*)&acc[mt][j][0]);   // row
            float2 hi = __half22float2(*(__half2*)&acc[mt][j][1]);   // row+8
            __half2 slo = __floats2half2_rn(1.f / (1.f + __expf(-lo.x)),
                                            1.f / (1.f + __expf(-lo.y)));
            __half2 shi = __floats2half2_rn(1.f / (1.f + __expf(-hi.x)),
                                            1.f / (1.f + __expf(-hi.y)));
            *(__half2*)(P + row * 264 + col)       = slo;
            *(__half2*)(P + (row + 8) * 264 + col) = shi;
        }
    __syncthreads();

    const int m = tid;             // 0..255 leaves
    __nv_bfloat16* dst = g_prob + (size_t)row0 * KDIM2 + t * 256 + m;
    for (int r = 0; r < 128; r++) {
        const __half* Pr = P + r * 264;
        float prod = 1.f;
#pragma unroll
        for (int n = 0; n < 8; n++) {
            int node = (1 << n) - 1 + (m >> (8 - n));
            float p = __half2float(Pr[node]);
            prod *= ((m >> (7 - n)) & 1) ? (1.f - p) : p;
        }
        dst[(size_t)r * KDIM2] = __float2bfloat16(prod);
    }
#undef K2_LOAD
}

// ---------------------------------------------------------------------------
// K3: bf16 mma GEMM out[96x256] = prob[96x2560] * leafp^T, 8 warps of 48x64
// grid (4, 171), 256 threads, 2-stage pipeline (1 sync/chunk), 2 CTAs/SM
// stage = A[96][72] + B[256][72] bf16 = 50688 B; x2 = 101376
// ---------------------------------------------------------------------------
#define K3_AB  13824u
#define K3_STG 50688u
__global__ __launch_bounds__(256, 2) void k3_mma(float* __restrict__ out) {
    extern __shared__ char smem[];
    const uint32_t sb = smem_u32(smem);
    const int ct   = blockIdx.x;
    const int row0 = blockIdx.y * 96;
    const int tid  = threadIdx.x;
    const int lane = tid & 31, wid = tid >> 5;
    const int wm = wid & 1, wn = wid >> 1;    // 2 x 4 warps: 48 rows x 64 cols

    const __nv_bfloat16* pA = g_prob + (size_t)row0 * KDIM2;
    const __nv_bfloat16* pB = g_lpb + (size_t)(ct * 256) * KDIM2;

    const int arow = lane & 15, akof = (lane >> 4) * 8;
    uint32_t aoff[3];
#pragma unroll
    for (int mt = 0; mt < 3; mt++)
        aoff[mt] = ((wm * 48 + mt * 16 + arow) * 72 + akof) * 2;
    const int bg = lane >> 3;
    const int brow = ((bg >> 1) * 8) + (lane & 7);
    const int bkof = (bg & 1) * 8;
    uint32_t boff[4];
#pragma unroll
    for (int q = 0; q < 4; q++)
        boff[q] = ((wn * 64 + q * 16 + brow) * 72 + bkof) * 2;

    float acc[3][8][4];
#pragma unroll
    for (int a = 0; a < 3; a++)
#pragma unroll
        for (int b = 0; b < 8; b++)
#pragma unroll
            for (int c = 0; c < 4; c++) acc[a][b][c] = 0.f;

    const int NC = KDIM2 / 64;   // 40

#define K3_LOAD(cc, stg) do {                                                     \
        const uint32_t st_ = sb + (uint32_t)(stg) * K3_STG;                       \
        const int k0_ = (cc) * 64;                                                \
        _Pragma("unroll")                                                         \
        for (int i_ = 0; i_ < 3; i_++) {                                          \
            int idx_ = tid + i_ * 256;                                            \
            int row_ = idx_ >> 3, ch_ = idx_ & 7;                                 \
            uint32_t d_ = st_ + row_ * 144 + ch_ * 16;                            \
            CPA(d_, (const char*)(pA + (size_t)row_ * KDIM2 + k0_ + ch_ * 8));    \
        }                                                                         \
        _Pragma("unroll")                                                         \
        for (int i_ = 0; i_ < 8; i_++) {                                          \
            int idx_ = tid + i_ * 256;                                            \
            int row_ = idx_ >> 3, ch_ = idx_ & 7;                                 \
            uint32_t d_ = st_ + K3_AB + row_ * 144 + ch_ * 16;                    \
            CPA(d_, (const char*)(pB + (size_t)row_ * KDIM2 + k0_ + ch_ * 8));    \
        }                                                                         \
    } while (0)

    K3_LOAD(0, 0); CPC();

    for (int c = 0; c < NC; c++) {
        CPW0();
        __syncthreads();
        if (c + 1 < NC) K3_LOAD(c + 1, (c + 1) & 1);
        CPC();
        const uint32_t st = sb + (uint32_t)(c & 1) * K3_STG;
#pragma unroll
        for (int ks = 0; ks < 4; ks++) {
            const uint32_t kb = ks * 32;
            uint32_t a[3][4];
#pragma unroll
            for (int mt = 0; mt < 3; mt++)
                ldsm4(a[mt], st + aoff[mt] + kb);
#pragma unroll
            for (int q = 0; q < 4; q++) {
                uint32_t b[4];
                ldsm4(b, st + K3_AB + boff[q] + kb);
#pragma unroll
                for (int mt = 0; mt < 3; mt++) {
                    mma_bf16(acc[mt][2 * q],     a[mt], b + 0);
                    mma_bf16(acc[mt][2 * q + 1], a[mt], b + 2);
                }
            }
        }
    }

    const int cbase = ct * 256 + wn * 64 + 2 * (lane & 3);
    const int rbase = row0 + wm * 48 + (lane >> 2);
#pragma unroll
    for (int mt = 0; mt < 3; mt++)
#pragma unroll
        for (int j = 0; j < 8; j++) {
            int col = cbase + j * 8;
            int r0w = rbase + mt * 16;
            if (col + 1 < CLASSES) {
                if (r0w < BATCH)
                    *(float2*)(out + (size_t)r0w * CLASSES + col) = make_float2(acc[mt][j][0], acc[mt][j][1]);
                if (r0w + 8 < BATCH)
                    *(float2*)(out + (size_t)(r0w + 8) * CLASSES + col) = make_float2(acc[mt][j][2], acc[mt][j][3]);
            } else if (col < CLASSES) {
                if (r0w < BATCH)     out[(size_t)r0w * CLASSES + col] = acc[mt][j][0];
                if (r0w + 8 < BATCH) out[(size_t)(r0w + 8) * CLASSES + col] = acc[mt][j][2];
            }
        }
#undef K3_LOAD
}

// ---------------------------------------------------------------------------
extern "C" void kernel_launch(void* const* d_in, const int* in_sizes, int n_in,
                              void* d_out, int out_size) {
    const float* x = nullptr;
    const float* wd = nullptr;
    const float* wl = nullptr;
    for (int i = 0; i < n_in; i++) {
        if (in_sizes[i] == BATCH * IN_DIM)              x = (const float*)d_in[i];
        else if (in_sizes[i] == NTREES * IN_DIM * NDEC) wd = (const float*)d_in[i];
        else if (in_sizes[i] == NTREES * 512 * CLASSES) wl = (const float*)d_in[i];
    }
    float* out = (float*)d_out;

    cudaFuncSetAttribute(k2_mma, cudaFuncAttributeMaxDynamicSharedMemorySize, 2 * K2_STG);
    cudaFuncSetAttribute(k3_mma, cudaFuncAttributeMaxDynamicSharedMemorySize, 2 * K3_STG);

    k0_prep<<<K1_BLKS + P2_BLKS + P1_BLKS, 256>>>(x, wd, wl);
    k2_mma<<<dim3(NTREES, BATCH / 128), 256, 2 * K2_STG>>>();
    k3_mma<<<dim3(4, (BATCH + 95) / 96), 256, 2 * K3_STG>>>(out);
}